// round 9
// baseline (speedup 1.0000x reference)
#include <cuda_runtime.h>
#include <math.h>
#include <stdint.h>

// Problem dims
#define B_    262144
#define DIN   153
#define DOUT  8
#define NE    8
#define H1_   128
#define H2_   64
#define GH_   64
#define GH2_  32
#define EPS   1e-5f

#define MTILE 128
#define NTHREADS 512
#define LDT   136    // row stride (floats) for transposed activation tiles (136 % 32 == 8)
#define LDG_  128    // row stride for GATE/ACC small tiles

// smem layout (floats)
#define OFF_XP   0                          // x_norm -> x_proj (in-place)  [160][136]
#define SZ_XP    (160*LDT)
#define OFF_H1   (OFF_XP + SZ_XP)           // g1 / h1  [128][136]
#define SZ_H1    (128*LDT)
#define OFF_G2   (OFF_H1 + 64*LDT)          // g2 inside H1 region (rows 64..95)
#define OFF_H2   (OFF_H1 + SZ_H1)           // h2^T [64][136]
#define SZ_H2    (64*LDT)
#define OFF_GATE (OFF_H2 + SZ_H2)           // gate^T [8][128]
#define SZ_GATE  (8*LDG_)
#define OFF_ACC  (OFF_GATE + SZ_GATE)       // acc^T [8][128]
#define SZ_ACC   (8*LDG_)
#define OFF_WS   (OFF_ACC + SZ_ACC)         // W staging: 2 x 24 x 168
#define SZ_WS    (2*24*168)
#define SMEM_FLOATS (OFF_WS + SZ_WS)        // 57984 floats = 231,936 B

// ---- packed f32x2 helpers (FFMA2 path for gating/combine) ----
__device__ __forceinline__ uint64_t fma2(uint64_t a, uint64_t b, uint64_t c) {
    uint64_t d;
    asm("fma.rn.f32x2 %0, %1, %2, %3;" : "=l"(d) : "l"(a), "l"(b), "l"(c));
    return d;
}
__device__ __forceinline__ uint64_t add2(uint64_t a, uint64_t b) {
    uint64_t d;
    asm("add.rn.f32x2 %0, %1, %2;" : "=l"(d) : "l"(a), "l"(b));
    return d;
}
__device__ __forceinline__ uint64_t dup2(float w) {
    uint64_t d;
    asm("mov.b64 %0, {%1, %1};" : "=l"(d) : "f"(w));
    return d;
}
__device__ __forceinline__ void unpack2(uint64_t v, float& lo, float& hi) {
    asm("mov.b64 {%0, %1}, %2;" : "=f"(lo), "=f"(hi) : "l"(v));
}

// tf32 round-to-nearest
__device__ __forceinline__ float tf32r(float x) {
    uint32_t u;
    asm("cvt.rna.tf32.f32 %0, %1;" : "=r"(u) : "f"(x));
    return __uint_as_float(u);
}

// ---- warp-level tf32 MMA m16n8k8 ----
__device__ __forceinline__ void mma8(float* d,
                                     uint32_t a0, uint32_t a1, uint32_t a2, uint32_t a3,
                                     uint32_t b0, uint32_t b1) {
    asm volatile(
        "mma.sync.aligned.m16n8k8.row.col.f32.tf32.tf32.f32 "
        "{%0,%1,%2,%3},{%4,%5,%6,%7},{%8,%9},{%0,%1,%2,%3};"
        : "+f"(d[0]), "+f"(d[1]), "+f"(d[2]), "+f"(d[3])
        : "r"(a0), "r"(a1), "r"(a2), "r"(a3), "r"(b0), "r"(b1));
}

// Tensor-core GEMM with smem-staged W (double-buffered 24-row k-chunks):
// O^T[N][128] = op(A^T[KT*8][128] @ W[K][N] + bias)
// 16 warps: row-group = warp&7 (16 rows), col-group = warp>>3 (n-tiles stride 2).
// In-place (Ot == As) is safe: the final chunk barrier separates all A reads
// from the per-element read-modify-write epilogue.
template<int K, int N, int LDN, bool RELU, bool RESID, bool TF32OUT>
__device__ __forceinline__ void mma_gemmT_st(const float* __restrict__ As,
                                             const float* __restrict__ Wg,
                                             const float* __restrict__ bias,
                                             float* __restrict__ Ot,
                                             float* __restrict__ wbuf,
                                             int warp, int lane, int tid)
{
    constexpr int KT  = (K + 7) / 8;        // k-steps
    constexpr int NCH = (KT + 2) / 3;       // chunks of 3 k-steps (24 k-rows)
    constexpr int NT  = (N + 7) / 8;        // n-tiles (even in all uses)
    constexpr int NTW = NT / 2;             // n-tiles per col-group
    constexpr int CHE = 24 * LDN;           // floats per staged chunk
    constexpr int LDI = (CHE + NTHREADS - 1) / NTHREADS;

    const int row0 = (warp & 7) * 16;
    const int colg = warp >> 3;             // 0 or 1
    const int gid  = lane >> 2;
    const int tig  = lane & 3;
    const int r_lo = row0 + gid;
    const int r_hi = r_lo + 8;

    // stage chunk 0 (zero-filled outside K/N)
    #pragma unroll
    for (int i = 0; i < LDI; i++) {
        int idx = tid + i * NTHREADS;
        if (idx < CHE) {
            int k = idx / LDN, n = idx % LDN;
            wbuf[idx] = (n < N && k < K) ? Wg[(size_t)k * N + n] : 0.f;
        }
    }
    __syncthreads();

    float acc[NTW][4];
    #pragma unroll
    for (int i = 0; i < NTW; i++)
        #pragma unroll
        for (int q = 0; q < 4; q++) acc[i][q] = 0.f;

    #pragma unroll 1
    for (int c = 0; c < NCH; c++) {
        // prefetch next chunk into registers (latency hidden behind mma)
        float pf[LDI];
        if (c + 1 < NCH) {
            #pragma unroll
            for (int i = 0; i < LDI; i++) {
                int idx = tid + i * NTHREADS;
                pf[i] = 0.f;
                if (idx < CHE) {
                    int k = idx / LDN, n = idx % LDN;
                    int kg = (c + 1) * 24 + k;
                    if (n < N && kg < K) pf[i] = Wg[(size_t)kg * N + n];
                }
            }
        }
        // mma over this chunk (no guards: staged zeros + zeroed A pad rows)
        const float* wb = wbuf + (c & 1) * CHE;
        #pragma unroll
        for (int kk = 0; kk < 3; kk++) {
            if (c * 3 + kk < KT) {
                const int k0 = (c * 3 + kk) * 8;
                const float* ap0 = As + (k0 + tig) * LDT;
                uint32_t a0 = __float_as_uint(ap0[r_lo]);
                uint32_t a1 = __float_as_uint(ap0[r_hi]);
                uint32_t a2 = __float_as_uint(ap0[4 * LDT + r_lo]);
                uint32_t a3 = __float_as_uint(ap0[4 * LDT + r_hi]);
                const float* wr0 = wb + (kk * 8 + tig) * LDN;
                #pragma unroll
                for (int i = 0; i < NTW; i++) {
                    const int col = (colg + 2 * i) * 8 + gid;
                    uint32_t b0 = __float_as_uint(wr0[col]);
                    uint32_t b1 = __float_as_uint(wr0[4 * LDN + col]);
                    mma8(acc[i], a0, a1, a2, a3, b0, b1);
                }
            }
        }
        // store prefetched chunk into the other buffer
        if (c + 1 < NCH) {
            float* wd = wbuf + ((c + 1) & 1) * CHE;
            #pragma unroll
            for (int i = 0; i < LDI; i++) {
                int idx = tid + i * NTHREADS;
                if (idx < CHE) wd[idx] = pf[i];
            }
        }
        __syncthreads();
    }

    // epilogue (all A reads complete: in-place safe)
    #pragma unroll
    for (int i = 0; i < NTW; i++) {
        const int nt = colg + 2 * i;
        #pragma unroll
        for (int h = 0; h < 2; h++) {
            const int col = nt * 8 + tig * 2 + h;
            if ((N % 8 == 0) || (col < N)) {
                const float b = bias[col];
                float v_lo = acc[i][h]     + b;
                float v_hi = acc[i][2 + h] + b;
                if (RELU) { v_lo = fmaxf(v_lo, 0.f); v_hi = fmaxf(v_hi, 0.f); }
                if (RESID) {
                    v_lo += As[col * LDT + r_lo];
                    v_hi += As[col * LDT + r_hi];
                }
                if (TF32OUT) { v_lo = tf32r(v_lo); v_hi = tf32r(v_hi); }
                Ot[col * LDT + r_lo] = v_lo;
                Ot[col * LDT + r_hi] = v_hi;
            }
        }
    }
}

// Scalar FFMA2 GEMM (gating path, fp32): O^T[N][128] = op(A^T @ W + bias)
template<int K, int N, int LDO, bool RELU>
__device__ __forceinline__ void gemmT(const float* __restrict__ As,
                                      const float* __restrict__ W,
                                      const float* __restrict__ bias,
                                      float* __restrict__ Ot,
                                      int tr, int tc)
{
    const int r0 = tr * 8;
    uint64_t acc[4][4];
    #pragma unroll
    for (int j = 0; j < 4; j++)
        #pragma unroll
        for (int q = 0; q < 4; q++) acc[j][q] = 0ull;

    const float* __restrict__ Wc[4];
    bool ok[4];
    #pragma unroll
    for (int j = 0; j < 4; j++) {
        if (32 * j < N) {
            int col = 32 * j + tc;
            ok[j] = (col < N);
            Wc[j] = W + (ok[j] ? col : 0);
        }
    }
    #pragma unroll 4
    for (int k = 0; k < K; k++) {
        const float* ap = As + k * LDT + r0;
        ulonglong2 A0 = *(const ulonglong2*)(ap);
        ulonglong2 A1 = *(const ulonglong2*)(ap + 4);
        #pragma unroll
        for (int j = 0; j < 4; j++) {
            if (32 * j < N) {
                uint64_t wd = dup2(Wc[j][(size_t)k * N]);
                acc[j][0] = fma2(A0.x, wd, acc[j][0]);
                acc[j][1] = fma2(A0.y, wd, acc[j][1]);
                acc[j][2] = fma2(A1.x, wd, acc[j][2]);
                acc[j][3] = fma2(A1.y, wd, acc[j][3]);
            }
        }
    }
    #pragma unroll
    for (int j = 0; j < 4; j++) {
        if (32 * j < N) {
            int col = 32 * j + tc;
            if (ok[j]) {
                const float b = bias[col];
                float* op = Ot + col * LDO + r0;
                #pragma unroll
                for (int q = 0; q < 4; q++) {
                    float lo, hi;
                    unpack2(acc[j][q], lo, hi);
                    float v0 = lo + b, v1 = hi + b;
                    if (RELU) { v0 = fmaxf(v0, 0.f); v1 = fmaxf(v1, 0.f); }
                    op[2 * q]     = v0;
                    op[2 * q + 1] = v1;
                }
            }
        }
    }
}

// Expert output GEMM (K=64, N=8) fused with gating-weighted accumulate.
__device__ __forceinline__ void gemm_combine(const float* __restrict__ As,   // h2^T [64][136]
                                             const float* __restrict__ W,   // [64][8]
                                             const float* __restrict__ bias,
                                             const float* __restrict__ gate,// [128] for this expert
                                             float* __restrict__ accT,      // [8][128]
                                             int tr, int tc)
{
    const int r0  = tr * 8;
    const int col = tc & 7;
    const int k0  = (tc >> 3) * 16;
    uint64_t acc[4] = {0ull, 0ull, 0ull, 0ull};
    const float* __restrict__ Wc = W + k0 * 8 + col;
    #pragma unroll 4
    for (int k = 0; k < 16; k++) {
        const float* ap = As + (k0 + k) * LDT + r0;
        ulonglong2 A0 = *(const ulonglong2*)(ap);
        ulonglong2 A1 = *(const ulonglong2*)(ap + 4);
        uint64_t wd = dup2(Wc[k * 8]);
        acc[0] = fma2(A0.x, wd, acc[0]);
        acc[1] = fma2(A0.y, wd, acc[1]);
        acc[2] = fma2(A1.x, wd, acc[2]);
        acc[3] = fma2(A1.y, wd, acc[3]);
    }
    #pragma unroll
    for (int q = 0; q < 4; q++) {
        double o16 = __shfl_down_sync(0xFFFFFFFFu,
                                      __longlong_as_double((long long)acc[q]), 16);
        acc[q] = add2(acc[q], (uint64_t)__double_as_longlong(o16));
        double o8 = __shfl_down_sync(0xFFFFFFFFu,
                                     __longlong_as_double((long long)acc[q]), 8);
        acc[q] = add2(acc[q], (uint64_t)__double_as_longlong(o8));
    }
    if (tc < 8) {
        const float b = bias[col];
        float* ap = accT + col * LDG_ + r0;
        #pragma unroll
        for (int q = 0; q < 4; q++) {
            float lo, hi;
            unpack2(acc[q], lo, hi);
            ap[2 * q]     += gate[r0 + 2 * q]     * (lo + b);
            ap[2 * q + 1] += gate[r0 + 2 * q + 1] * (hi + b);
        }
    }
}

__global__ __launch_bounds__(NTHREADS, 1)
void moe_fused_kernel(const float* __restrict__ x,
                      const float* __restrict__ ln_in_g, const float* __restrict__ ln_in_b,
                      const float* __restrict__ Wp,  const float* __restrict__ bp,
                      const float* __restrict__ Wg1, const float* __restrict__ bg1,
                      const float* __restrict__ Wg2, const float* __restrict__ bg2,
                      const float* __restrict__ Wg3, const float* __restrict__ bg3,
                      const float* __restrict__ We1, const float* __restrict__ be1,
                      const float* __restrict__ We2, const float* __restrict__ be2,
                      const float* __restrict__ We3, const float* __restrict__ be3,
                      const float* __restrict__ ln_out_g, const float* __restrict__ ln_out_b,
                      float* __restrict__ out)
{
    extern __shared__ float sm[];
    const int tid  = threadIdx.x;
    const int tr   = tid >> 5, tc = tid & 31;
    const int warp = tid >> 5, lane = tid & 31;
    const int row0 = blockIdx.x * MTILE;
    float* ws = sm + OFF_WS;

    // zero combine accumulator and XP pad rows (k = 153..159)
    for (int i = tid; i < SZ_ACC; i += NTHREADS) sm[OFF_ACC + i] = 0.f;
    for (int i = tid; i < (160 - DIN) * LDT; i += NTHREADS)
        sm[OFF_XP + DIN * LDT + i] = 0.f;

    // ---- input LayerNorm -> XP (tf32-rounded) ----
    for (int rr = warp; rr < MTILE; rr += 16) {
        const float* xr = x + (size_t)(row0 + rr) * DIN;
        float v[5];
        float s = 0.f, ss = 0.f;
        #pragma unroll
        for (int i = 0; i < 5; i++) {
            int k = i * 32 + lane;
            float val = (k < DIN) ? xr[k] : 0.f;
            v[i] = val; s += val; ss += val * val;
        }
        #pragma unroll
        for (int o = 16; o > 0; o >>= 1) {
            s  += __shfl_xor_sync(0xFFFFFFFFu, s,  o);
            ss += __shfl_xor_sync(0xFFFFFFFFu, ss, o);
        }
        const float m   = s * (1.f / DIN);
        const float var = ss * (1.f / DIN) - m * m;
        const float inv = rsqrtf(var + EPS);
        #pragma unroll
        for (int i = 0; i < 5; i++) {
            int k = i * 32 + lane;
            if (k < DIN)
                sm[OFF_XP + k * LDT + rr] =
                    tf32r((v[i] - m) * inv * ln_in_g[k] + ln_in_b[k]);
        }
    }
    __syncthreads();

    // ---- x_proj = relu(x_norm @ Wp + bp) + x_norm  (tensor, in-place) ----
    mma_gemmT_st<DIN, DIN, 168, true, true, true>(sm + OFF_XP, Wp, bp,
                                                  sm + OFF_XP, ws, warp, lane, tid);
    __syncthreads();

    // ---- gating MLP (scalar fp32) ----
    gemmT<DIN, GH_, LDT, true>(sm + OFF_XP, Wg1, bg1, sm + OFF_H1, tr, tc);
    __syncthreads();
    gemmT<GH_, GH2_, LDT, true>(sm + OFF_H1, Wg2, bg2, sm + OFF_G2, tr, tc);
    __syncthreads();
    gemmT<GH2_, 8, LDG_, false>(sm + OFF_G2, Wg3, bg3, sm + OFF_GATE, tr, tc);
    __syncthreads();

    // ---- softmax over experts, write gating output ----
    if (tid < MTILE) {
        float l[8];
        float mx = -INFINITY;
        #pragma unroll
        for (int e = 0; e < NE; e++) { l[e] = sm[OFF_GATE + e * LDG_ + tid]; mx = fmaxf(mx, l[e]); }
        float s = 0.f;
        #pragma unroll
        for (int e = 0; e < NE; e++) { l[e] = expf(l[e] - mx); s += l[e]; }
        const float invs = 1.f / s;
        float* gw = out + (size_t)B_ * 8 + (size_t)(row0 + tid) * 8;
        #pragma unroll
        for (int e = 0; e < NE; e++) {
            float g = l[e] * invs;
            sm[OFF_GATE + e * LDG_ + tid] = g;
            gw[e] = g;
        }
    }
    __syncthreads();

    // ---- experts: sequential, staged tensor GEMMs + scalar combine ----
    #pragma unroll 1
    for (int e = 0; e < NE; e++) {
        mma_gemmT_st<DIN, H1_, 136, true, false, true>(
            sm + OFF_XP, We1 + (size_t)e * DIN * H1_, be1 + e * H1_,
            sm + OFF_H1, ws, warp, lane, tid);
        __syncthreads();
        mma_gemmT_st<H1_, H2_, 72, true, false, false>(
            sm + OFF_H1, We2 + (size_t)e * H1_ * H2_, be2 + e * H2_,
            sm + OFF_H2, ws, warp, lane, tid);
        __syncthreads();
        gemm_combine(sm + OFF_H2, We3 + (size_t)e * H2_ * DOUT, be3 + e * DOUT,
                     sm + OFF_GATE + e * LDG_, sm + OFF_ACC, tr, tc);
        __syncthreads();
    }

    // ---- output LayerNorm over 8 dims, write out ----
    if (tid < MTILE) {
        float y[8];
        float s = 0.f;
        #pragma unroll
        for (int e = 0; e < DOUT; e++) { y[e] = sm[OFF_ACC + e * LDG_ + tid]; s += y[e]; }
        const float m = s * 0.125f;
        float var = 0.f;
        #pragma unroll
        for (int e = 0; e < DOUT; e++) { float d = y[e] - m; var += d * d; }
        var *= 0.125f;
        const float inv = rsqrtf(var + EPS);
        float* op = out + (size_t)(row0 + tid) * 8;
        #pragma unroll
        for (int e = 0; e < DOUT; e++)
            op[e] = (y[e] - m) * inv * ln_out_g[e] + ln_out_b[e];
    }
}

extern "C" void kernel_launch(void* const* d_in, const int* in_sizes, int n_in,
                              void* d_out, int out_size)
{
    const float* x       = (const float*)d_in[0];
    const float* ln_in_g = (const float*)d_in[1];
    const float* ln_in_b = (const float*)d_in[2];
    const float* Wp      = (const float*)d_in[3];
    const float* bp      = (const float*)d_in[4];
    const float* Wg1     = (const float*)d_in[5];
    const float* bg1     = (const float*)d_in[6];
    const float* Wg2     = (const float*)d_in[7];
    const float* bg2     = (const float*)d_in[8];
    const float* Wg3     = (const float*)d_in[9];
    const float* bg3     = (const float*)d_in[10];
    const float* We1     = (const float*)d_in[11];
    const float* be1     = (const float*)d_in[12];
    const float* We2     = (const float*)d_in[13];
    const float* be2     = (const float*)d_in[14];
    const float* We3     = (const float*)d_in[15];
    const float* be3     = (const float*)d_in[16];
    const float* ln_out_g= (const float*)d_in[17];
    const float* ln_out_b= (const float*)d_in[18];
    float* out = (float*)d_out;

    const size_t smem = SMEM_FLOATS * sizeof(float);
    cudaFuncSetAttribute(moe_fused_kernel,
                         cudaFuncAttributeMaxDynamicSharedMemorySize, (int)smem);

    moe_fused_kernel<<<B_ / MTILE, NTHREADS, smem>>>(
        x, ln_in_g, ln_in_b, Wp, bp, Wg1, bg1, Wg2, bg2, Wg3, bg3,
        We1, be1, We2, be2, We3, be3, ln_out_g, ln_out_b, out);
}

// round 10
// speedup vs baseline: 1.8150x; 1.8150x over previous
#include <cuda_runtime.h>
#include <math.h>
#include <stdint.h>

// Problem dims
#define B_    262144
#define DIN   153
#define DOUT  8
#define NE    8
#define H1_   128
#define H2_   64
#define GH_   64
#define GH2_  32
#define EPS   1e-5f

#define MTILE 128
#define NTHREADS 512
#define LDT   136    // padded row stride (floats) for transposed [K][128] smem tiles
#define KPAD  160    // padded K rows (DIN=153 -> 160) for mma A tiles

// smem layout (floats) — same as R7 (217,600 B)
#define OFF_XP   0
#define SZ_XP    (KPAD*LDT)
#define OFF_XS   (OFF_XP + SZ_XP)
#define SZ_XS    (KPAD*LDT)
#define OFF_G2   (OFF_XS + GH_*LDT)
#define OFF_H2   (OFF_XS + SZ_XS)
#define SZ_H2    (H2_*LDT)
#define OFF_GATE (OFF_H2 + SZ_H2)
#define SZ_GATE  (8*LDT)
#define OFF_ACC  (OFF_GATE + SZ_GATE)
#define SZ_ACC   (8*LDT)
#define SMEM_FLOATS (OFF_ACC + SZ_ACC)

// ---- packed-weight global scratch (written by pack_kernel each launch) ----
// layout: frag (ks, nt) -> 64 floats: [0..31]=b0 lanes, [32..63]=b1 lanes
// lane l: tig = l&3, gid = l>>2; b0 = W[(ks*8+tig)*N + nt*8+gid], b1 = +4 k-rows
#define KT_P   20   // Wp:  K=153 -> 20 k-steps
#define NT_P   20   // Wp:  N=153 -> 20 n-tiles (padded)
#define KT_E1  20   // We1: K=153
#define NT_E1  16   // We1: N=128
#define KT_E2  16   // We2: K=128
#define NT_E2  8    // We2: N=64
#define SZ_PWP  (KT_P*NT_P*64)            // 25600
#define SZ_PWE1 (KT_E1*NT_E1*64)          // 20480 per expert
#define SZ_PWE2 (KT_E2*NT_E2*64)          // 8192 per expert
__device__ float g_pWp [SZ_PWP];
__device__ float g_pWe1[NE*SZ_PWE1];
__device__ float g_pWe2[NE*SZ_PWE2];
#define PACK_TOTAL (SZ_PWP + NE*SZ_PWE1 + NE*SZ_PWE2)   // 254,976

__device__ __forceinline__ float pack_elem(const float* __restrict__ W,
                                           int K, int N, int NT, int rel)
{
    int ks   = rel / (NT * 64);
    int r    = rel % (NT * 64);
    int nt   = r / 64;
    int l2   = r % 64;
    int half = l2 >> 5;
    int lane = l2 & 31;
    int tig  = lane & 3;
    int gid  = lane >> 2;
    int k = ks * 8 + half * 4 + tig;
    int n = nt * 8 + gid;
    return (k < K && n < N) ? W[(size_t)k * N + n] : 0.f;
}

__global__ void pack_kernel(const float* __restrict__ Wp,
                            const float* __restrict__ We1,
                            const float* __restrict__ We2)
{
    int idx = blockIdx.x * blockDim.x + threadIdx.x;
    if (idx >= PACK_TOTAL) return;
    if (idx < SZ_PWP) {
        g_pWp[idx] = pack_elem(Wp, DIN, DIN, NT_P, idx);
        return;
    }
    idx -= SZ_PWP;
    if (idx < NE * SZ_PWE1) {
        int e = idx / SZ_PWE1, rel = idx % SZ_PWE1;
        g_pWe1[idx] = pack_elem(We1 + (size_t)e * DIN * H1_, DIN, H1_, NT_E1, rel);
        return;
    }
    idx -= NE * SZ_PWE1;
    {
        int e = idx / SZ_PWE2, rel = idx % SZ_PWE2;
        g_pWe2[idx] = pack_elem(We2 + (size_t)e * H1_ * H2_, H1_, H2_, NT_E2, rel);
    }
}

// ---- packed f32x2 helpers ----
__device__ __forceinline__ uint64_t fma2(uint64_t a, uint64_t b, uint64_t c) {
    uint64_t d;
    asm("fma.rn.f32x2 %0, %1, %2, %3;" : "=l"(d) : "l"(a), "l"(b), "l"(c));
    return d;
}
__device__ __forceinline__ uint64_t add2(uint64_t a, uint64_t b) {
    uint64_t d;
    asm("add.rn.f32x2 %0, %1, %2;" : "=l"(d) : "l"(a), "l"(b));
    return d;
}
__device__ __forceinline__ uint64_t dup2(float w) {
    uint64_t d;
    asm("mov.b64 %0, {%1, %1};" : "=l"(d) : "f"(w));
    return d;
}
__device__ __forceinline__ void unpack2(uint64_t v, float& lo, float& hi) {
    asm("mov.b64 {%0, %1}, %2;" : "=f"(lo), "=f"(hi) : "l"(v));
}
__device__ __forceinline__ float tf32r(float x) {
    uint32_t u;
    asm("cvt.rna.tf32.f32 %0, %1;" : "=r"(u) : "f"(x));
    return __uint_as_float(u);
}

// ---- warp-level tf32 MMA m16n8k8 ----
__device__ __forceinline__ void mma8(float* d,
                                     uint32_t a0, uint32_t a1, uint32_t a2, uint32_t a3,
                                     uint32_t b0, uint32_t b1) {
    asm volatile(
        "mma.sync.aligned.m16n8k8.row.col.f32.tf32.tf32.f32 "
        "{%0,%1,%2,%3},{%4,%5,%6,%7},{%8,%9},{%0,%1,%2,%3};"
        : "+f"(d[0]), "+f"(d[1]), "+f"(d[2]), "+f"(d[3])
        : "r"(a0), "r"(a1), "r"(a2), "r"(a3), "r"(b0), "r"(b1));
}

// Tensor-core GEMM with PACKED global B (coalesced 1-wavefront fragment loads):
// O^T[N][128] = op(A^T @ W + bias).
// 16 warps: row-group = warp&7 (16 rows), col-group = warp>>3 (n-tiles stride 2).
template<int KT, int NT, int N, bool RELU, bool RESID, bool TF32OUT>
__device__ __forceinline__ void mma_pk(const float* __restrict__ As,
                                       const float* __restrict__ pk,
                                       const float* __restrict__ bias,
                                       float* __restrict__ Ot,
                                       int warp, int lane)
{
    constexpr int NTW = NT / 2;
    const int row0 = (warp & 7) * 16;
    const int colg = warp >> 3;
    const int gid  = lane >> 2;
    const int tig  = lane & 3;
    const int r_lo = row0 + gid;
    const int r_hi = r_lo + 8;

    float acc[NTW][4];
    #pragma unroll
    for (int i = 0; i < NTW; i++)
        #pragma unroll
        for (int q = 0; q < 4; q++) acc[i][q] = 0.f;

    const float* __restrict__ pb0 = pk + colg * 64 + lane;

    #pragma unroll 2
    for (int ks = 0; ks < KT; ks++) {
        const float* ap0 = As + (ks * 8 + tig) * LDT;
        uint32_t a0 = __float_as_uint(ap0[r_lo]);
        uint32_t a1 = __float_as_uint(ap0[r_hi]);
        uint32_t a2 = __float_as_uint(ap0[4 * LDT + r_lo]);
        uint32_t a3 = __float_as_uint(ap0[4 * LDT + r_hi]);
        const float* __restrict__ pb = pb0 + ks * (NT * 64);
        #pragma unroll
        for (int i = 0; i < NTW; i++) {
            uint32_t b0 = __float_as_uint(pb[i * 128]);
            uint32_t b1 = __float_as_uint(pb[i * 128 + 32]);
            mma8(acc[i], a0, a1, a2, a3, b0, b1);
        }
    }

    // epilogue (padded n-tiles guarded only when N not multiple of 8)
    #pragma unroll
    for (int i = 0; i < NTW; i++) {
        const int nt = colg + 2 * i;
        #pragma unroll
        for (int h = 0; h < 2; h++) {
            const int col = nt * 8 + tig * 2 + h;
            if ((N % 8 == 0) || (col < N)) {
                const float b = bias[col];
                float v_lo = acc[i][h]     + b;
                float v_hi = acc[i][2 + h] + b;
                if (RELU) { v_lo = fmaxf(v_lo, 0.f); v_hi = fmaxf(v_hi, 0.f); }
                if (RESID) {
                    v_lo += As[col * LDT + r_lo];
                    v_hi += As[col * LDT + r_hi];
                }
                if (TF32OUT) { v_lo = tf32r(v_lo); v_hi = tf32r(v_hi); }
                Ot[col * LDT + r_lo] = v_lo;
                Ot[col * LDT + r_hi] = v_hi;
            }
        }
    }
}

// Scalar FFMA2 GEMM (gating path, fp32)
template<int K, int N, bool RELU>
__device__ __forceinline__ void gemmT(const float* __restrict__ As,
                                      const float* __restrict__ W,
                                      const float* __restrict__ bias,
                                      float* __restrict__ Ot,
                                      int tr, int tc)
{
    const int r0 = tr * 8;
    uint64_t acc[4][4];
    #pragma unroll
    for (int j = 0; j < 4; j++)
        #pragma unroll
        for (int q = 0; q < 4; q++) acc[j][q] = 0ull;

    const float* __restrict__ Wc[4];
    bool ok[4];
    #pragma unroll
    for (int j = 0; j < 4; j++) {
        if (32 * j < N) {
            int col = 32 * j + tc;
            ok[j] = (col < N);
            Wc[j] = W + (ok[j] ? col : 0);
        }
    }
    #pragma unroll 4
    for (int k = 0; k < K; k++) {
        const float* ap = As + k * LDT + r0;
        ulonglong2 A0 = *(const ulonglong2*)(ap);
        ulonglong2 A1 = *(const ulonglong2*)(ap + 4);
        #pragma unroll
        for (int j = 0; j < 4; j++) {
            if (32 * j < N) {
                uint64_t wd = dup2(Wc[j][(size_t)k * N]);
                acc[j][0] = fma2(A0.x, wd, acc[j][0]);
                acc[j][1] = fma2(A0.y, wd, acc[j][1]);
                acc[j][2] = fma2(A1.x, wd, acc[j][2]);
                acc[j][3] = fma2(A1.y, wd, acc[j][3]);
            }
        }
    }
    #pragma unroll
    for (int j = 0; j < 4; j++) {
        if (32 * j < N) {
            int col = 32 * j + tc;
            if (ok[j]) {
                const float b = bias[col];
                float* op = Ot + col * LDT + r0;
                #pragma unroll
                for (int q = 0; q < 4; q++) {
                    float lo, hi;
                    unpack2(acc[j][q], lo, hi);
                    float v0 = lo + b, v1 = hi + b;
                    if (RELU) { v0 = fmaxf(v0, 0.f); v1 = fmaxf(v1, 0.f); }
                    op[2 * q]     = v0;
                    op[2 * q + 1] = v1;
                }
            }
        }
    }
}

// Expert output GEMM (K=64, N=8) fused with gating-weighted accumulate.
__device__ __forceinline__ void gemm_combine(const float* __restrict__ As,
                                             const float* __restrict__ W,
                                             const float* __restrict__ bias,
                                             const float* __restrict__ gate,
                                             float* __restrict__ accT,
                                             int tr, int tc)
{
    const int r0  = tr * 8;
    const int col = tc & 7;
    const int k0  = (tc >> 3) * 16;
    uint64_t acc[4] = {0ull, 0ull, 0ull, 0ull};
    const float* __restrict__ Wc = W + k0 * 8 + col;
    #pragma unroll 4
    for (int k = 0; k < 16; k++) {
        const float* ap = As + (k0 + k) * LDT + r0;
        ulonglong2 A0 = *(const ulonglong2*)(ap);
        ulonglong2 A1 = *(const ulonglong2*)(ap + 4);
        uint64_t wd = dup2(Wc[k * 8]);
        acc[0] = fma2(A0.x, wd, acc[0]);
        acc[1] = fma2(A0.y, wd, acc[1]);
        acc[2] = fma2(A1.x, wd, acc[2]);
        acc[3] = fma2(A1.y, wd, acc[3]);
    }
    #pragma unroll
    for (int q = 0; q < 4; q++) {
        double o16 = __shfl_down_sync(0xFFFFFFFFu,
                                      __longlong_as_double((long long)acc[q]), 16);
        acc[q] = add2(acc[q], (uint64_t)__double_as_longlong(o16));
        double o8 = __shfl_down_sync(0xFFFFFFFFu,
                                     __longlong_as_double((long long)acc[q]), 8);
        acc[q] = add2(acc[q], (uint64_t)__double_as_longlong(o8));
    }
    if (tc < 8) {
        const float b = bias[col];
        float* ap = accT + col * LDT + r0;
        #pragma unroll
        for (int q = 0; q < 4; q++) {
            float lo, hi;
            unpack2(acc[q], lo, hi);
            ap[2 * q]     += gate[r0 + 2 * q]     * (lo + b);
            ap[2 * q + 1] += gate[r0 + 2 * q + 1] * (hi + b);
        }
    }
}

__global__ __launch_bounds__(NTHREADS, 1)
void moe_fused_kernel(const float* __restrict__ x,
                      const float* __restrict__ ln_in_g, const float* __restrict__ ln_in_b,
                      const float* __restrict__ bp,
                      const float* __restrict__ Wg1, const float* __restrict__ bg1,
                      const float* __restrict__ Wg2, const float* __restrict__ bg2,
                      const float* __restrict__ Wg3, const float* __restrict__ bg3,
                      const float* __restrict__ be1,
                      const float* __restrict__ be2,
                      const float* __restrict__ We3, const float* __restrict__ be3,
                      const float* __restrict__ ln_out_g, const float* __restrict__ ln_out_b,
                      float* __restrict__ out)
{
    extern __shared__ float sm[];
    const int tid  = threadIdx.x;
    const int tr   = tid >> 5, tc = tid & 31;
    const int warp = tid >> 5, lane = tid & 31;
    const int row0 = blockIdx.x * MTILE;

    // zero the combine accumulator and A-pad rows (k=153..159 of XP and XS)
    for (int i = tid; i < SZ_ACC; i += NTHREADS) sm[OFF_ACC + i] = 0.f;
    for (int i = tid; i < (KPAD - DIN) * LDT; i += NTHREADS) {
        sm[OFF_XP + DIN * LDT + i] = 0.f;
        sm[OFF_XS + DIN * LDT + i] = 0.f;
    }

    // ---- input LayerNorm -> XS (tf32-rounded) ----
    for (int rr = warp; rr < MTILE; rr += 16) {
        const float* xr = x + (size_t)(row0 + rr) * DIN;
        float v[5];
        float s = 0.f, ss = 0.f;
        #pragma unroll
        for (int i = 0; i < 5; i++) {
            int k = i * 32 + lane;
            float val = (k < DIN) ? xr[k] : 0.f;
            v[i] = val; s += val; ss += val * val;
        }
        #pragma unroll
        for (int o = 16; o > 0; o >>= 1) {
            s  += __shfl_xor_sync(0xFFFFFFFFu, s,  o);
            ss += __shfl_xor_sync(0xFFFFFFFFu, ss, o);
        }
        const float m   = s * (1.f / DIN);
        const float var = ss * (1.f / DIN) - m * m;
        const float inv = rsqrtf(var + EPS);
        #pragma unroll
        for (int i = 0; i < 5; i++) {
            int k = i * 32 + lane;
            if (k < DIN)
                sm[OFF_XS + k * LDT + rr] =
                    tf32r((v[i] - m) * inv * ln_in_g[k] + ln_in_b[k]);
        }
    }
    __syncthreads();

    // ---- x_proj = relu(x_norm @ Wp + bp) + x_norm  (tensor, packed B) ----
    mma_pk<KT_P, NT_P, DIN, true, true, true>(sm + OFF_XS, g_pWp, bp,
                                              sm + OFF_XP, warp, lane);
    __syncthreads();

    // ---- gating MLP (scalar fp32) ----
    gemmT<DIN, GH_, true>(sm + OFF_XP, Wg1, bg1, sm + OFF_XS, tr, tc);
    __syncthreads();
    gemmT<GH_, GH2_, true>(sm + OFF_XS, Wg2, bg2, sm + OFF_G2, tr, tc);
    __syncthreads();
    gemmT<GH2_, 8, false>(sm + OFF_G2, Wg3, bg3, sm + OFF_GATE, tr, tc);
    __syncthreads();

    // ---- softmax over experts, write gating output ----
    if (tid < MTILE) {
        float l[8];
        float mx = -INFINITY;
        #pragma unroll
        for (int e = 0; e < NE; e++) { l[e] = sm[OFF_GATE + e * LDT + tid]; mx = fmaxf(mx, l[e]); }
        float s = 0.f;
        #pragma unroll
        for (int e = 0; e < NE; e++) { l[e] = expf(l[e] - mx); s += l[e]; }
        const float invs = 1.f / s;
        float* gw = out + (size_t)B_ * 8 + (size_t)(row0 + tid) * 8;
        #pragma unroll
        for (int e = 0; e < NE; e++) {
            float g = l[e] * invs;
            sm[OFF_GATE + e * LDT + tid] = g;
            gw[e] = g;
        }
    }
    __syncthreads();

    // ---- experts: sequential, packed tensor GEMMs + scalar combine ----
    #pragma unroll 1
    for (int e = 0; e < NE; e++) {
        mma_pk<KT_E1, NT_E1, H1_, true, false, true>(
            sm + OFF_XP, g_pWe1 + (size_t)e * SZ_PWE1, be1 + e * H1_,
            sm + OFF_XS, warp, lane);
        __syncthreads();
        mma_pk<KT_E2, NT_E2, H2_, true, false, false>(
            sm + OFF_XS, g_pWe2 + (size_t)e * SZ_PWE2, be2 + e * H2_,
            sm + OFF_H2, warp, lane);
        __syncthreads();
        gemm_combine(sm + OFF_H2, We3 + (size_t)e * H2_ * DOUT, be3 + e * DOUT,
                     sm + OFF_GATE + e * LDT, sm + OFF_ACC, tr, tc);
        // no barrier needed: combine reads H2/GATE, writes ACC; next We1 writes XS
        // only, and the barrier after it orders everything else.
    }
    __syncthreads();

    // ---- output LayerNorm over 8 dims, write out ----
    if (tid < MTILE) {
        float y[8];
        float s = 0.f;
        #pragma unroll
        for (int e = 0; e < DOUT; e++) { y[e] = sm[OFF_ACC + e * LDT + tid]; s += y[e]; }
        const float m = s * 0.125f;
        float var = 0.f;
        #pragma unroll
        for (int e = 0; e < DOUT; e++) { float d = y[e] - m; var += d * d; }
        var *= 0.125f;
        const float inv = rsqrtf(var + EPS);
        float* op = out + (size_t)(row0 + tid) * 8;
        #pragma unroll
        for (int e = 0; e < DOUT; e++)
            op[e] = (y[e] - m) * inv * ln_out_g[e] + ln_out_b[e];
    }
}

extern "C" void kernel_launch(void* const* d_in, const int* in_sizes, int n_in,
                              void* d_out, int out_size)
{
    const float* x       = (const float*)d_in[0];
    const float* ln_in_g = (const float*)d_in[1];
    const float* ln_in_b = (const float*)d_in[2];
    const float* Wp      = (const float*)d_in[3];
    const float* bp      = (const float*)d_in[4];
    const float* Wg1     = (const float*)d_in[5];
    const float* bg1     = (const float*)d_in[6];
    const float* Wg2     = (const float*)d_in[7];
    const float* bg2     = (const float*)d_in[8];
    const float* Wg3     = (const float*)d_in[9];
    const float* bg3     = (const float*)d_in[10];
    const float* We1     = (const float*)d_in[11];
    const float* be1     = (const float*)d_in[12];
    const float* We2     = (const float*)d_in[13];
    const float* be2     = (const float*)d_in[14];
    const float* We3     = (const float*)d_in[15];
    const float* be3     = (const float*)d_in[16];
    const float* ln_out_g= (const float*)d_in[17];
    const float* ln_out_b= (const float*)d_in[18];
    float* out = (float*)d_out;

    pack_kernel<<<(PACK_TOTAL + 255) / 256, 256>>>(Wp, We1, We2);

    const size_t smem = SMEM_FLOATS * sizeof(float);
    cudaFuncSetAttribute(moe_fused_kernel,
                         cudaFuncAttributeMaxDynamicSharedMemorySize, (int)smem);

    moe_fused_kernel<<<B_ / MTILE, NTHREADS, smem>>>(
        x, ln_in_g, ln_in_b, bp, Wg1, bg1, Wg2, bg2, Wg3, bg3,
        be1, be2, We3, be3, ln_out_g, ln_out_b, out);
}

// round 11
// speedup vs baseline: 2.2117x; 1.2185x over previous
#include <cuda_runtime.h>
#include <math.h>
#include <stdint.h>

// Problem dims
#define B_    262144
#define DIN   153
#define DOUT  8
#define NE    8
#define H1_   128
#define H2_   64
#define GH_   64
#define GH2_  32
#define EPS   1e-5f

#define MTILE 128
#define NTHREADS 512
#define LDT   136    // padded row stride (floats) for transposed [K][128] smem tiles
#define KPAD  160    // padded K rows (DIN=153 -> 160) for mma A tiles

// smem layout (floats) — 217,600 B
#define OFF_XP   0
#define SZ_XP    (KPAD*LDT)
#define OFF_XS   (OFF_XP + SZ_XP)
#define SZ_XS    (KPAD*LDT)
#define OFF_G2   (OFF_XS + GH_*LDT)
#define OFF_H2   (OFF_XS + SZ_XS)
#define SZ_H2    (H2_*LDT)
#define OFF_GATE (OFF_H2 + SZ_H2)
#define SZ_GATE  (8*LDT)
#define OFF_ACC  (OFF_GATE + SZ_GATE)
#define SZ_ACC   (8*LDT)
#define SMEM_FLOATS (OFF_ACC + SZ_ACC)

// ---- packed-weight global scratch (fragment-lane order, written per launch) ----
// frag (ks, nt) -> 64 floats: [0..31]=b0 lanes, [32..63]=b1 lanes
// lane l: tig=l&3, gid=l>>2; b0 = W[(ks*8+tig)*N + nt*8+gid], b1 = +4 k-rows
#define KT_P   20   // Wp:  K=153
#define NT_P   20   // Wp:  N=153 (padded)
#define KT_E1  20   // We1: K=153
#define NT_E1  16   // We1: N=128
#define KT_E2  16   // We2: K=128
#define NT_E2  8    // We2: N=64
#define KT_G1  20   // Wg1: K=153
#define NT_G1  8    // Wg1: N=64
#define SZ_PWP  (KT_P*NT_P*64)
#define SZ_PWE1 (KT_E1*NT_E1*64)
#define SZ_PWE2 (KT_E2*NT_E2*64)
#define SZ_PWG1 (KT_G1*NT_G1*64)
__device__ float g_pWp [SZ_PWP];
__device__ float g_pWe1[NE*SZ_PWE1];
__device__ float g_pWe2[NE*SZ_PWE2];
__device__ float g_pWg1[SZ_PWG1];
#define PACK_TOTAL (SZ_PWP + NE*SZ_PWE1 + NE*SZ_PWE2 + SZ_PWG1)

__device__ __forceinline__ float pack_elem(const float* __restrict__ W,
                                           int K, int N, int NT, int rel)
{
    int ks   = rel / (NT * 64);
    int r    = rel % (NT * 64);
    int nt   = r / 64;
    int l2   = r % 64;
    int half = l2 >> 5;
    int lane = l2 & 31;
    int tig  = lane & 3;
    int gid  = lane >> 2;
    int k = ks * 8 + half * 4 + tig;
    int n = nt * 8 + gid;
    return (k < K && n < N) ? W[(size_t)k * N + n] : 0.f;
}

__global__ void pack_kernel(const float* __restrict__ Wp,
                            const float* __restrict__ We1,
                            const float* __restrict__ We2,
                            const float* __restrict__ Wg1)
{
    int idx = blockIdx.x * blockDim.x + threadIdx.x;
    if (idx >= PACK_TOTAL) return;
    if (idx < SZ_PWP) {
        g_pWp[idx] = pack_elem(Wp, DIN, DIN, NT_P, idx);
        return;
    }
    idx -= SZ_PWP;
    if (idx < NE * SZ_PWE1) {
        int e = idx / SZ_PWE1, rel = idx % SZ_PWE1;
        g_pWe1[idx] = pack_elem(We1 + (size_t)e * DIN * H1_, DIN, H1_, NT_E1, rel);
        return;
    }
    idx -= NE * SZ_PWE1;
    if (idx < NE * SZ_PWE2) {
        int e = idx / SZ_PWE2, rel = idx % SZ_PWE2;
        g_pWe2[idx] = pack_elem(We2 + (size_t)e * H1_ * H2_, H1_, H2_, NT_E2, rel);
        return;
    }
    idx -= NE * SZ_PWE2;
    g_pWg1[idx] = pack_elem(Wg1, DIN, GH_, NT_G1, idx);
}

// ---- packed f32x2 helpers ----
__device__ __forceinline__ uint64_t fma2(uint64_t a, uint64_t b, uint64_t c) {
    uint64_t d;
    asm("fma.rn.f32x2 %0, %1, %2, %3;" : "=l"(d) : "l"(a), "l"(b), "l"(c));
    return d;
}
__device__ __forceinline__ uint64_t add2(uint64_t a, uint64_t b) {
    uint64_t d;
    asm("add.rn.f32x2 %0, %1, %2;" : "=l"(d) : "l"(a), "l"(b));
    return d;
}
__device__ __forceinline__ uint64_t dup2(float w) {
    uint64_t d;
    asm("mov.b64 %0, {%1, %1};" : "=l"(d) : "f"(w));
    return d;
}
__device__ __forceinline__ void unpack2(uint64_t v, float& lo, float& hi) {
    asm("mov.b64 {%0, %1}, %2;" : "=f"(lo), "=f"(hi) : "l"(v));
}
__device__ __forceinline__ float tf32r(float x) {
    uint32_t u;
    asm("cvt.rna.tf32.f32 %0, %1;" : "=r"(u) : "f"(x));
    return __uint_as_float(u);
}

// ---- warp-level tf32 MMA m16n8k8 ----
__device__ __forceinline__ void mma8(float* d,
                                     uint32_t a0, uint32_t a1, uint32_t a2, uint32_t a3,
                                     uint32_t b0, uint32_t b1) {
    asm volatile(
        "mma.sync.aligned.m16n8k8.row.col.f32.tf32.tf32.f32 "
        "{%0,%1,%2,%3},{%4,%5,%6,%7},{%8,%9},{%0,%1,%2,%3};"
        : "+f"(d[0]), "+f"(d[1]), "+f"(d[2]), "+f"(d[3])
        : "r"(a0), "r"(a1), "r"(a2), "r"(a3), "r"(b0), "r"(b1));
}

// Tensor-core GEMM, packed global B, 4 row-groups x 4 col-groups:
// each warp: 32 rows (2 m-tiles) x NT/4 n-tiles. B fragment reused across m-tiles.
template<int KT, int NT, int N, bool RELU, bool RESID, bool TF32OUT>
__device__ __forceinline__ void mma_pk(const float* __restrict__ As,
                                       const float* __restrict__ pk,
                                       const float* __restrict__ bias,
                                       float* __restrict__ Ot,
                                       int warp, int lane)
{
    constexpr int NTW = NT / 4;
    const int rg   = warp & 3;
    const int cg   = warp >> 2;
    const int gid  = lane >> 2;
    const int tig  = lane & 3;
    const int r_lo = rg * 32 + gid;
    const int r_hi = r_lo + 8;

    float acc[NTW][2][4];
    #pragma unroll
    for (int i = 0; i < NTW; i++)
        #pragma unroll
        for (int m = 0; m < 2; m++)
            #pragma unroll
            for (int q = 0; q < 4; q++) acc[i][m][q] = 0.f;

    const float* __restrict__ pb0 = pk + cg * 64 + lane;

    #pragma unroll 2
    for (int ks = 0; ks < KT; ks++) {
        const float* ap0 = As + (ks * 8 + tig) * LDT;
        const float* ap1 = ap0 + 4 * LDT;
        uint32_t a0 = __float_as_uint(ap0[r_lo]);
        uint32_t a1 = __float_as_uint(ap0[r_hi]);
        uint32_t a2 = __float_as_uint(ap1[r_lo]);
        uint32_t a3 = __float_as_uint(ap1[r_hi]);
        uint32_t c0 = __float_as_uint(ap0[r_lo + 16]);
        uint32_t c1 = __float_as_uint(ap0[r_hi + 16]);
        uint32_t c2 = __float_as_uint(ap1[r_lo + 16]);
        uint32_t c3 = __float_as_uint(ap1[r_hi + 16]);
        const float* __restrict__ pb = pb0 + ks * (NT * 64);
        #pragma unroll
        for (int i = 0; i < NTW; i++) {
            uint32_t b0 = __float_as_uint(pb[i * 256]);
            uint32_t b1 = __float_as_uint(pb[i * 256 + 32]);
            mma8(acc[i][0], a0, a1, a2, a3, b0, b1);
            mma8(acc[i][1], c0, c1, c2, c3, b0, b1);
        }
    }

    // epilogue
    #pragma unroll
    for (int i = 0; i < NTW; i++) {
        const int nt = cg + 4 * i;
        #pragma unroll
        for (int m = 0; m < 2; m++) {
            const int rl = r_lo + m * 16;
            const int rh = r_hi + m * 16;
            #pragma unroll
            for (int h = 0; h < 2; h++) {
                const int col = nt * 8 + tig * 2 + h;
                if ((N % 8 == 0) || (col < N)) {
                    const float b = bias[col];
                    float v_lo = acc[i][m][h]     + b;
                    float v_hi = acc[i][m][2 + h] + b;
                    if (RELU) { v_lo = fmaxf(v_lo, 0.f); v_hi = fmaxf(v_hi, 0.f); }
                    if (RESID) {
                        v_lo += As[col * LDT + rl];
                        v_hi += As[col * LDT + rh];
                    }
                    if (TF32OUT) { v_lo = tf32r(v_lo); v_hi = tf32r(v_hi); }
                    Ot[col * LDT + rl] = v_lo;
                    Ot[col * LDT + rh] = v_hi;
                }
            }
        }
    }
}

// Scalar FFMA2 GEMM (small gating layers, fp32)
template<int K, int N, bool RELU>
__device__ __forceinline__ void gemmT(const float* __restrict__ As,
                                      const float* __restrict__ W,
                                      const float* __restrict__ bias,
                                      float* __restrict__ Ot,
                                      int tr, int tc)
{
    const int r0 = tr * 8;
    uint64_t acc[4][4];
    #pragma unroll
    for (int j = 0; j < 4; j++)
        #pragma unroll
        for (int q = 0; q < 4; q++) acc[j][q] = 0ull;

    const float* __restrict__ Wc[4];
    bool ok[4];
    #pragma unroll
    for (int j = 0; j < 4; j++) {
        if (32 * j < N) {
            int col = 32 * j + tc;
            ok[j] = (col < N);
            Wc[j] = W + (ok[j] ? col : 0);
        }
    }
    #pragma unroll 4
    for (int k = 0; k < K; k++) {
        const float* ap = As + k * LDT + r0;
        ulonglong2 A0 = *(const ulonglong2*)(ap);
        ulonglong2 A1 = *(const ulonglong2*)(ap + 4);
        #pragma unroll
        for (int j = 0; j < 4; j++) {
            if (32 * j < N) {
                uint64_t wd = dup2(Wc[j][(size_t)k * N]);
                acc[j][0] = fma2(A0.x, wd, acc[j][0]);
                acc[j][1] = fma2(A0.y, wd, acc[j][1]);
                acc[j][2] = fma2(A1.x, wd, acc[j][2]);
                acc[j][3] = fma2(A1.y, wd, acc[j][3]);
            }
        }
    }
    #pragma unroll
    for (int j = 0; j < 4; j++) {
        if (32 * j < N) {
            int col = 32 * j + tc;
            if (ok[j]) {
                const float b = bias[col];
                float* op = Ot + col * LDT + r0;
                #pragma unroll
                for (int q = 0; q < 4; q++) {
                    float lo, hi;
                    unpack2(acc[j][q], lo, hi);
                    float v0 = lo + b, v1 = hi + b;
                    if (RELU) { v0 = fmaxf(v0, 0.f); v1 = fmaxf(v1, 0.f); }
                    op[2 * q]     = v0;
                    op[2 * q + 1] = v1;
                }
            }
        }
    }
}

// Expert output GEMM (K=64, N=8) fused with gating-weighted accumulate.
__device__ __forceinline__ void gemm_combine(const float* __restrict__ As,
                                             const float* __restrict__ W,
                                             const float* __restrict__ bias,
                                             const float* __restrict__ gate,
                                             float* __restrict__ accT,
                                             int tr, int tc)
{
    const int r0  = tr * 8;
    const int col = tc & 7;
    const int k0  = (tc >> 3) * 16;
    uint64_t acc[4] = {0ull, 0ull, 0ull, 0ull};
    const float* __restrict__ Wc = W + k0 * 8 + col;
    #pragma unroll 4
    for (int k = 0; k < 16; k++) {
        const float* ap = As + (k0 + k) * LDT + r0;
        ulonglong2 A0 = *(const ulonglong2*)(ap);
        ulonglong2 A1 = *(const ulonglong2*)(ap + 4);
        uint64_t wd = dup2(Wc[k * 8]);
        acc[0] = fma2(A0.x, wd, acc[0]);
        acc[1] = fma2(A0.y, wd, acc[1]);
        acc[2] = fma2(A1.x, wd, acc[2]);
        acc[3] = fma2(A1.y, wd, acc[3]);
    }
    #pragma unroll
    for (int q = 0; q < 4; q++) {
        double o16 = __shfl_down_sync(0xFFFFFFFFu,
                                      __longlong_as_double((long long)acc[q]), 16);
        acc[q] = add2(acc[q], (uint64_t)__double_as_longlong(o16));
        double o8 = __shfl_down_sync(0xFFFFFFFFu,
                                     __longlong_as_double((long long)acc[q]), 8);
        acc[q] = add2(acc[q], (uint64_t)__double_as_longlong(o8));
    }
    if (tc < 8) {
        const float b = bias[col];
        float* ap = accT + col * LDT + r0;
        #pragma unroll
        for (int q = 0; q < 4; q++) {
            float lo, hi;
            unpack2(acc[q], lo, hi);
            ap[2 * q]     += gate[r0 + 2 * q]     * (lo + b);
            ap[2 * q + 1] += gate[r0 + 2 * q + 1] * (hi + b);
        }
    }
}

__global__ __launch_bounds__(NTHREADS, 1)
void moe_fused_kernel(const float* __restrict__ x,
                      const float* __restrict__ ln_in_g, const float* __restrict__ ln_in_b,
                      const float* __restrict__ bp,
                      const float* __restrict__ bg1,
                      const float* __restrict__ Wg2, const float* __restrict__ bg2,
                      const float* __restrict__ Wg3, const float* __restrict__ bg3,
                      const float* __restrict__ be1,
                      const float* __restrict__ be2,
                      const float* __restrict__ We3, const float* __restrict__ be3,
                      const float* __restrict__ ln_out_g, const float* __restrict__ ln_out_b,
                      float* __restrict__ out)
{
    extern __shared__ float sm[];
    const int tid  = threadIdx.x;
    const int tr   = tid >> 5, tc = tid & 31;
    const int warp = tid >> 5, lane = tid & 31;
    const int row0 = blockIdx.x * MTILE;

    // zero the combine accumulator and A-pad rows (k=153..159 of XP and XS)
    for (int i = tid; i < SZ_ACC; i += NTHREADS) sm[OFF_ACC + i] = 0.f;
    for (int i = tid; i < (KPAD - DIN) * LDT; i += NTHREADS) {
        sm[OFF_XP + DIN * LDT + i] = 0.f;
        sm[OFF_XS + DIN * LDT + i] = 0.f;
    }

    // ---- input LayerNorm -> XS (tf32-rounded) ----
    for (int rr = warp; rr < MTILE; rr += 16) {
        const float* xr = x + (size_t)(row0 + rr) * DIN;
        float v[5];
        float s = 0.f, ss = 0.f;
        #pragma unroll
        for (int i = 0; i < 5; i++) {
            int k = i * 32 + lane;
            float val = (k < DIN) ? xr[k] : 0.f;
            v[i] = val; s += val; ss += val * val;
        }
        #pragma unroll
        for (int o = 16; o > 0; o >>= 1) {
            s  += __shfl_xor_sync(0xFFFFFFFFu, s,  o);
            ss += __shfl_xor_sync(0xFFFFFFFFu, ss, o);
        }
        const float m   = s * (1.f / DIN);
        const float var = ss * (1.f / DIN) - m * m;
        const float inv = rsqrtf(var + EPS);
        #pragma unroll
        for (int i = 0; i < 5; i++) {
            int k = i * 32 + lane;
            if (k < DIN)
                sm[OFF_XS + k * LDT + rr] =
                    tf32r((v[i] - m) * inv * ln_in_g[k] + ln_in_b[k]);
        }
    }
    __syncthreads();

    // ---- x_proj = relu(x_norm @ Wp + bp) + x_norm  (tensor, packed B) ----
    mma_pk<KT_P, NT_P, DIN, true, true, true>(sm + OFF_XS, g_pWp, bp,
                                              sm + OFF_XP, warp, lane);
    __syncthreads();

    // ---- gating MLP: g1 on tensor, g2/g3 scalar fp32 ----
    mma_pk<KT_G1, NT_G1, GH_, true, false, false>(sm + OFF_XP, g_pWg1, bg1,
                                                  sm + OFF_XS, warp, lane);
    __syncthreads();
    gemmT<GH_, GH2_, true>(sm + OFF_XS, Wg2, bg2, sm + OFF_G2, tr, tc);
    __syncthreads();
    gemmT<GH2_, 8, false>(sm + OFF_G2, Wg3, bg3, sm + OFF_GATE, tr, tc);
    __syncthreads();

    // ---- softmax over experts, write gating output ----
    if (tid < MTILE) {
        float l[8];
        float mx = -INFINITY;
        #pragma unroll
        for (int e = 0; e < NE; e++) { l[e] = sm[OFF_GATE + e * LDT + tid]; mx = fmaxf(mx, l[e]); }
        float s = 0.f;
        #pragma unroll
        for (int e = 0; e < NE; e++) { l[e] = expf(l[e] - mx); s += l[e]; }
        const float invs = 1.f / s;
        float* gw = out + (size_t)B_ * 8 + (size_t)(row0 + tid) * 8;
        #pragma unroll
        for (int e = 0; e < NE; e++) {
            float g = l[e] * invs;
            sm[OFF_GATE + e * LDT + tid] = g;
            gw[e] = g;
        }
    }
    __syncthreads();

    // ---- experts: sequential, packed tensor GEMMs + scalar combine ----
    #pragma unroll 1
    for (int e = 0; e < NE; e++) {
        mma_pk<KT_E1, NT_E1, H1_, true, false, true>(
            sm + OFF_XP, g_pWe1 + (size_t)e * SZ_PWE1, be1 + e * H1_,
            sm + OFF_XS, warp, lane);
        __syncthreads();
        mma_pk<KT_E2, NT_E2, H2_, true, false, false>(
            sm + OFF_XS, g_pWe2 + (size_t)e * SZ_PWE2, be2 + e * H2_,
            sm + OFF_H2, warp, lane);
        __syncthreads();
        gemm_combine(sm + OFF_H2, We3 + (size_t)e * H2_ * DOUT, be3 + e * DOUT,
                     sm + OFF_GATE + e * LDT, sm + OFF_ACC, tr, tc);
        // no barrier needed: combine reads H2/GATE, writes ACC; next We1 writes XS
        // only, and the barrier after it orders everything else.
    }
    __syncthreads();

    // ---- output LayerNorm over 8 dims, write out ----
    if (tid < MTILE) {
        float y[8];
        float s = 0.f;
        #pragma unroll
        for (int e = 0; e < DOUT; e++) { y[e] = sm[OFF_ACC + e * LDT + tid]; s += y[e]; }
        const float m = s * 0.125f;
        float var = 0.f;
        #pragma unroll
        for (int e = 0; e < DOUT; e++) { float d = y[e] - m; var += d * d; }
        var *= 0.125f;
        const float inv = rsqrtf(var + EPS);
        float* op = out + (size_t)(row0 + tid) * 8;
        #pragma unroll
        for (int e = 0; e < DOUT; e++)
            op[e] = (y[e] - m) * inv * ln_out_g[e] + ln_out_b[e];
    }
}

extern "C" void kernel_launch(void* const* d_in, const int* in_sizes, int n_in,
                              void* d_out, int out_size)
{
    const float* x       = (const float*)d_in[0];
    const float* ln_in_g = (const float*)d_in[1];
    const float* ln_in_b = (const float*)d_in[2];
    const float* Wp      = (const float*)d_in[3];
    const float* bp      = (const float*)d_in[4];
    const float* Wg1     = (const float*)d_in[5];
    const float* bg1     = (const float*)d_in[6];
    const float* Wg2     = (const float*)d_in[7];
    const float* bg2     = (const float*)d_in[8];
    const float* Wg3     = (const float*)d_in[9];
    const float* bg3     = (const float*)d_in[10];
    const float* We1     = (const float*)d_in[11];
    const float* be1     = (const float*)d_in[12];
    const float* We2     = (const float*)d_in[13];
    const float* be2     = (const float*)d_in[14];
    const float* We3     = (const float*)d_in[15];
    const float* be3     = (const float*)d_in[16];
    const float* ln_out_g= (const float*)d_in[17];
    const float* ln_out_b= (const float*)d_in[18];
    float* out = (float*)d_out;

    pack_kernel<<<(PACK_TOTAL + 255) / 256, 256>>>(Wp, We1, We2, Wg1);

    const size_t smem = SMEM_FLOATS * sizeof(float);
    cudaFuncSetAttribute(moe_fused_kernel,
                         cudaFuncAttributeMaxDynamicSharedMemorySize, (int)smem);

    moe_fused_kernel<<<B_ / MTILE, NTHREADS, smem>>>(
        x, ln_in_g, ln_in_b, bp, bg1, Wg2, bg2, Wg3, bg3,
        be1, be2, We3, be3, ln_out_g, ln_out_b, out);
}

// round 12
// speedup vs baseline: 2.3753x; 1.0740x over previous
#include <cuda_runtime.h>
#include <math.h>
#include <stdint.h>

// Problem dims
#define B_    262144
#define DIN   153
#define DOUT  8
#define NE    8
#define H1_   128
#define H2_   64
#define GH_   64
#define GH2_  32
#define EPS   1e-5f

#define MTILE 128
#define NTHREADS 512

// k-step / n-tile counts
#define KS_P   20   // Wp:  K=153 -> 20 k-steps
#define NT_P   20   // Wp:  N=153 (padded to 160)
#define KS_G1  20   // Wg1: K=153
#define NT_G1  8    // Wg1: N=64
#define KS_E1  20   // We1: K=153
#define NT_E1  16   // We1: N=128
#define KS_E2  16   // We2: K=128
#define NT_E2  8    // We2: N=64

// ---- smem layout (floats) ----
// AF (fragment-major) buffer: per k-step: 4 rg x 2 half x 32 lanes x 4 floats = 1024
#define AF_SZ(KS)  ((KS)*1024)
#define OFF_XP   0                         // x_proj AF [20 ks]  (20480)
#define OFF_UN   (OFF_XP + AF_SZ(KS_P))    // union: x_norm AF(20480) / g1+g2 / h1 AF(16384)
#define SZ_UN    AF_SZ(KS_P)
#define OFF_G1   OFF_UN                    // g1 linear [64][128]
#define OFF_G2   (OFF_UN + 64*128)         // g2 linear [32][128]
#define OFF_H2   (OFF_UN + SZ_UN)          // h2 linear [64][128]   (8192)
#define OFF_GATE (OFF_H2 + 64*128)         // gate [8][128]
#define OFF_ACC  (OFF_GATE + 8*128)        // acc  [8][128]
#define SMEM_FLOATS (OFF_ACC + 8*128)      // 51200 floats = 204,800 B

// ---- packed-weight global scratch ----
// frag (ks, nt) = 64 floats; lane l slot: [2l]=b0, [2l+1]=b1
// lane l: tig=l&3, gid=l>>2; b0 = W[(ks*8+tig)*N + nt*8+gid], b1 = +4 k-rows
#define SZ_PWP  (KS_P*NT_P*64)
#define SZ_PWG1 (KS_G1*NT_G1*64)
#define SZ_PWE1 (KS_E1*NT_E1*64)
#define SZ_PWE2 (KS_E2*NT_E2*64)
__device__ float g_pWp [SZ_PWP];
__device__ float g_pWg1[SZ_PWG1];
__device__ float g_pWe1[NE*SZ_PWE1];
__device__ float g_pWe2[NE*SZ_PWE2];
#define PACK_TOTAL (SZ_PWP + SZ_PWG1 + NE*SZ_PWE1 + NE*SZ_PWE2)

__device__ __forceinline__ float pack_elem(const float* __restrict__ W,
                                           int K, int N, int NT, int rel)
{
    int ks    = rel / (NT * 64);
    int r     = rel % (NT * 64);
    int nt    = r / 64;
    int f     = r % 64;
    int lane  = f >> 1;
    int which = f & 1;
    int tig   = lane & 3;
    int gid   = lane >> 2;
    int k = ks * 8 + which * 4 + tig;
    int n = nt * 8 + gid;
    return (k < K && n < N) ? W[(size_t)k * N + n] : 0.f;
}

__global__ void pack_kernel(const float* __restrict__ Wp,
                            const float* __restrict__ Wg1,
                            const float* __restrict__ We1,
                            const float* __restrict__ We2)
{
    int idx = blockIdx.x * blockDim.x + threadIdx.x;
    if (idx >= PACK_TOTAL) return;
    if (idx < SZ_PWP) { g_pWp[idx] = pack_elem(Wp, DIN, DIN, NT_P, idx); return; }
    idx -= SZ_PWP;
    if (idx < SZ_PWG1) { g_pWg1[idx] = pack_elem(Wg1, DIN, GH_, NT_G1, idx); return; }
    idx -= SZ_PWG1;
    if (idx < NE * SZ_PWE1) {
        int e = idx / SZ_PWE1, rel = idx % SZ_PWE1;
        g_pWe1[idx] = pack_elem(We1 + (size_t)e * DIN * H1_, DIN, H1_, NT_E1, rel);
        return;
    }
    idx -= NE * SZ_PWE1;
    {
        int e = idx / SZ_PWE2, rel = idx % SZ_PWE2;
        g_pWe2[idx] = pack_elem(We2 + (size_t)e * H1_ * H2_, H1_, H2_, NT_E2, rel);
    }
}

// ---- AF (fragment-major) addressing: value (k, r) ----
// float index = (((ks*4+rg)*2+half)*32 + gid*4+tig)*4 + kbit*2 + rbit
__device__ __forceinline__ int af_idx(int k, int r) {
    int ks = k >> 3, tigc = k & 3, kbit = (k >> 2) & 1;
    int rg = r >> 5, half = (r >> 4) & 1, gidc = r & 7, rbit = (r >> 3) & 1;
    return ((((ks * 4 + rg) * 2 + half) * 32 + gidc * 4 + tigc) << 2) + kbit * 2 + rbit;
}

// ---- packed f32x2 helpers ----
__device__ __forceinline__ uint64_t fma2(uint64_t a, uint64_t b, uint64_t c) {
    uint64_t d;
    asm("fma.rn.f32x2 %0, %1, %2, %3;" : "=l"(d) : "l"(a), "l"(b), "l"(c));
    return d;
}
__device__ __forceinline__ uint64_t add2(uint64_t a, uint64_t b) {
    uint64_t d;
    asm("add.rn.f32x2 %0, %1, %2;" : "=l"(d) : "l"(a), "l"(b));
    return d;
}
__device__ __forceinline__ uint64_t dup2(float w) {
    uint64_t d;
    asm("mov.b64 %0, {%1, %1};" : "=l"(d) : "f"(w));
    return d;
}
__device__ __forceinline__ void unpack2(uint64_t v, float& lo, float& hi) {
    asm("mov.b64 {%0, %1}, %2;" : "=f"(lo), "=f"(hi) : "l"(v));
}
__device__ __forceinline__ float tf32r(float x) {
    uint32_t u;
    asm("cvt.rna.tf32.f32 %0, %1;" : "=r"(u) : "f"(x));
    return __uint_as_float(u);
}

// ---- warp-level tf32 MMA m16n8k8 ----
__device__ __forceinline__ void mma8(float* d,
                                     uint32_t a0, uint32_t a1, uint32_t a2, uint32_t a3,
                                     uint32_t b0, uint32_t b1) {
    asm volatile(
        "mma.sync.aligned.m16n8k8.row.col.f32.tf32.tf32.f32 "
        "{%0,%1,%2,%3},{%4,%5,%6,%7},{%8,%9},{%0,%1,%2,%3};"
        : "+f"(d[0]), "+f"(d[1]), "+f"(d[2]), "+f"(d[3])
        : "r"(a0), "r"(a1), "r"(a2), "r"(a3), "r"(b0), "r"(b1));
}

// Tensor-core GEMM: AF-layout A (2x LDS.128/warp/k-step), packed B (LDG.64).
// 16 warps: rg = warp&3 (32 rows), cg = warp>>2 (n-tiles stride 4).
// AFOUT: write AF layout (tf32-rounded) for tensor consumers; else linear [col*128+r].
template<int KS, int NT, int N, bool RELU, bool RESID, bool AFOUT>
__device__ __forceinline__ void mma_pk(const float* __restrict__ Aaf,
                                       const float* __restrict__ pk,
                                       const float* __restrict__ bias,
                                       float* __restrict__ Ot,
                                       int warp, int lane)
{
    constexpr int NTW = NT / 4;
    const int rg  = warp & 3;
    const int cg  = warp >> 2;
    const int gid = lane >> 2;
    const int tig = lane & 3;

    float acc[NTW][2][4];
    #pragma unroll
    for (int i = 0; i < NTW; i++)
        #pragma unroll
        for (int m = 0; m < 2; m++)
            #pragma unroll
            for (int q = 0; q < 4; q++) acc[i][m][q] = 0.f;

    const float4* __restrict__ afb = reinterpret_cast<const float4*>(Aaf);
    const float2* __restrict__ pb0 = reinterpret_cast<const float2*>(pk) + cg * 32 + lane;

    #pragma unroll
    for (int ks = 0; ks < KS; ks++) {
        const float4* ap = afb + ((ks * 4 + rg) * 2) * 32 + lane;
        float4 A = ap[0];      // a0,a1,a2,a3 (rows rg*32+gid/+8)
        float4 C = ap[32];     // c0..c3     (rows +16/+24)
        const float2* pb = pb0 + ks * (NT * 32);
        #pragma unroll
        for (int i = 0; i < NTW; i++) {
            float2 b = pb[i * 128];
            uint32_t b0 = __float_as_uint(b.x), b1 = __float_as_uint(b.y);
            mma8(acc[i][0], __float_as_uint(A.x), __float_as_uint(A.y),
                            __float_as_uint(A.z), __float_as_uint(A.w), b0, b1);
            mma8(acc[i][1], __float_as_uint(C.x), __float_as_uint(C.y),
                            __float_as_uint(C.z), __float_as_uint(C.w), b0, b1);
        }
    }

    // epilogue
    #pragma unroll
    for (int i = 0; i < NTW; i++) {
        const int nt = cg + 4 * i;
        #pragma unroll
        for (int m = 0; m < 2; m++) {
            const int rl = rg * 32 + gid + m * 16;
            const int rh = rl + 8;
            #pragma unroll
            for (int h = 0; h < 2; h++) {
                const int col = nt * 8 + tig * 2 + h;
                if ((N % 8 == 0) || (col < N)) {
                    const float b = bias[col];
                    float v_lo = acc[i][m][h]     + b;
                    float v_hi = acc[i][m][2 + h] + b;
                    if (RELU) { v_lo = fmaxf(v_lo, 0.f); v_hi = fmaxf(v_hi, 0.f); }
                    if (RESID) {
                        v_lo += Aaf[af_idx(col, rl)];
                        v_hi += Aaf[af_idx(col, rh)];
                    }
                    if (AFOUT) {
                        Ot[af_idx(col, rl)] = tf32r(v_lo);
                        Ot[af_idx(col, rh)] = tf32r(v_hi);
                    } else {
                        Ot[col * 128 + rl] = v_lo;
                        Ot[col * 128 + rh] = v_hi;
                    }
                }
            }
        }
    }
}

// Scalar FFMA2 GEMM (small gating layers, fp32), linear A stride 128
template<int K, int N, bool RELU>
__device__ __forceinline__ void gemmT(const float* __restrict__ As,
                                      const float* __restrict__ W,
                                      const float* __restrict__ bias,
                                      float* __restrict__ Ot,
                                      int tr, int tc)
{
    const int r0 = tr * 8;
    uint64_t acc[4][4];
    #pragma unroll
    for (int j = 0; j < 4; j++)
        #pragma unroll
        for (int q = 0; q < 4; q++) acc[j][q] = 0ull;

    const float* __restrict__ Wc[4];
    bool ok[4];
    #pragma unroll
    for (int j = 0; j < 4; j++) {
        if (32 * j < N) {
            int col = 32 * j + tc;
            ok[j] = (col < N);
            Wc[j] = W + (ok[j] ? col : 0);
        }
    }
    #pragma unroll 4
    for (int k = 0; k < K; k++) {
        const float* ap = As + k * 128 + r0;
        ulonglong2 A0 = *(const ulonglong2*)(ap);
        ulonglong2 A1 = *(const ulonglong2*)(ap + 4);
        #pragma unroll
        for (int j = 0; j < 4; j++) {
            if (32 * j < N) {
                uint64_t wd = dup2(Wc[j][(size_t)k * N]);
                acc[j][0] = fma2(A0.x, wd, acc[j][0]);
                acc[j][1] = fma2(A0.y, wd, acc[j][1]);
                acc[j][2] = fma2(A1.x, wd, acc[j][2]);
                acc[j][3] = fma2(A1.y, wd, acc[j][3]);
            }
        }
    }
    #pragma unroll
    for (int j = 0; j < 4; j++) {
        if (32 * j < N) {
            int col = 32 * j + tc;
            if (ok[j]) {
                const float b = bias[col];
                float* op = Ot + col * 128 + r0;
                #pragma unroll
                for (int q = 0; q < 4; q++) {
                    float lo, hi;
                    unpack2(acc[j][q], lo, hi);
                    float v0 = lo + b, v1 = hi + b;
                    if (RELU) { v0 = fmaxf(v0, 0.f); v1 = fmaxf(v1, 0.f); }
                    op[2 * q]     = v0;
                    op[2 * q + 1] = v1;
                }
            }
        }
    }
}

// Expert output GEMM (K=64, N=8) fused with gating-weighted accumulate (h2 linear).
__device__ __forceinline__ void gemm_combine(const float* __restrict__ As,
                                             const float* __restrict__ W,
                                             const float* __restrict__ bias,
                                             const float* __restrict__ gate,
                                             float* __restrict__ accT,
                                             int tr, int tc)
{
    const int r0  = tr * 8;
    const int col = tc & 7;
    const int k0  = (tc >> 3) * 16;
    uint64_t acc[4] = {0ull, 0ull, 0ull, 0ull};
    const float* __restrict__ Wc = W + k0 * 8 + col;
    #pragma unroll 4
    for (int k = 0; k < 16; k++) {
        const float* ap = As + (k0 + k) * 128 + r0;
        ulonglong2 A0 = *(const ulonglong2*)(ap);
        ulonglong2 A1 = *(const ulonglong2*)(ap + 4);
        uint64_t wd = dup2(Wc[k * 8]);
        acc[0] = fma2(A0.x, wd, acc[0]);
        acc[1] = fma2(A0.y, wd, acc[1]);
        acc[2] = fma2(A1.x, wd, acc[2]);
        acc[3] = fma2(A1.y, wd, acc[3]);
    }
    #pragma unroll
    for (int q = 0; q < 4; q++) {
        double o16 = __shfl_down_sync(0xFFFFFFFFu,
                                      __longlong_as_double((long long)acc[q]), 16);
        acc[q] = add2(acc[q], (uint64_t)__double_as_longlong(o16));
        double o8 = __shfl_down_sync(0xFFFFFFFFu,
                                     __longlong_as_double((long long)acc[q]), 8);
        acc[q] = add2(acc[q], (uint64_t)__double_as_longlong(o8));
    }
    if (tc < 8) {
        const float b = bias[col];
        float* ap = accT + col * 128 + r0;
        #pragma unroll
        for (int q = 0; q < 4; q++) {
            float lo, hi;
            unpack2(acc[q], lo, hi);
            ap[2 * q]     += gate[r0 + 2 * q]     * (lo + b);
            ap[2 * q + 1] += gate[r0 + 2 * q + 1] * (hi + b);
        }
    }
}

__global__ __launch_bounds__(NTHREADS, 1)
void moe_fused_kernel(const float* __restrict__ x,
                      const float* __restrict__ ln_in_g, const float* __restrict__ ln_in_b,
                      const float* __restrict__ bp,
                      const float* __restrict__ bg1,
                      const float* __restrict__ Wg2, const float* __restrict__ bg2,
                      const float* __restrict__ Wg3, const float* __restrict__ bg3,
                      const float* __restrict__ be1,
                      const float* __restrict__ be2,
                      const float* __restrict__ We3, const float* __restrict__ be3,
                      const float* __restrict__ ln_out_g, const float* __restrict__ ln_out_b,
                      float* __restrict__ out)
{
    extern __shared__ float sm[];
    const int tid  = threadIdx.x;
    const int tr   = tid >> 5, tc = tid & 31;
    const int warp = tid >> 5, lane = tid & 31;
    const int row0 = blockIdx.x * MTILE;

    // zero: ACC, and the last k-step AF blocks of XP and XN (k = 152..159 slots)
    for (int i = tid; i < 8 * 128; i += NTHREADS) sm[OFF_ACC + i] = 0.f;
    for (int i = tid; i < 1024; i += NTHREADS) {
        sm[OFF_XP + (KS_P - 1) * 1024 + i] = 0.f;
        sm[OFF_UN + (KS_P - 1) * 1024 + i] = 0.f;
    }

    // ---- input LayerNorm -> XN (AF layout, tf32-rounded) ----
    for (int rr = warp; rr < MTILE; rr += 16) {
        const float* xr = x + (size_t)(row0 + rr) * DIN;
        float v[5];
        float s = 0.f, ss = 0.f;
        #pragma unroll
        for (int i = 0; i < 5; i++) {
            int k = i * 32 + lane;
            float val = (k < DIN) ? xr[k] : 0.f;
            v[i] = val; s += val; ss += val * val;
        }
        #pragma unroll
        for (int o = 16; o > 0; o >>= 1) {
            s  += __shfl_xor_sync(0xFFFFFFFFu, s,  o);
            ss += __shfl_xor_sync(0xFFFFFFFFu, ss, o);
        }
        const float m   = s * (1.f / DIN);
        const float var = ss * (1.f / DIN) - m * m;
        const float inv = rsqrtf(var + EPS);
        #pragma unroll
        for (int i = 0; i < 5; i++) {
            int k = i * 32 + lane;
            if (k < DIN)
                sm[OFF_UN + af_idx(k, rr)] =
                    tf32r((v[i] - m) * inv * ln_in_g[k] + ln_in_b[k]);
        }
    }
    __syncthreads();

    // ---- x_proj = relu(x_norm @ Wp + bp) + x_norm  -> XP (AF) ----
    mma_pk<KS_P, NT_P, DIN, true, true, true>(sm + OFF_UN, g_pWp, bp,
                                              sm + OFF_XP, warp, lane);
    __syncthreads();

    // ---- gating: g1 tensor (linear out), g2/g3 scalar ----
    mma_pk<KS_G1, NT_G1, GH_, true, false, false>(sm + OFF_XP, g_pWg1, bg1,
                                                  sm + OFF_G1, warp, lane);
    __syncthreads();
    gemmT<GH_, GH2_, true>(sm + OFF_G1, Wg2, bg2, sm + OFF_G2, tr, tc);
    __syncthreads();
    gemmT<GH2_, 8, false>(sm + OFF_G2, Wg3, bg3, sm + OFF_GATE, tr, tc);
    __syncthreads();

    // ---- softmax over experts, write gating output ----
    if (tid < MTILE) {
        float l[8];
        float mx = -INFINITY;
        #pragma unroll
        for (int e = 0; e < NE; e++) { l[e] = sm[OFF_GATE + e * 128 + tid]; mx = fmaxf(mx, l[e]); }
        float s = 0.f;
        #pragma unroll
        for (int e = 0; e < NE; e++) { l[e] = expf(l[e] - mx); s += l[e]; }
        const float invs = 1.f / s;
        float* gw = out + (size_t)B_ * 8 + (size_t)(row0 + tid) * 8;
        #pragma unroll
        for (int e = 0; e < NE; e++) {
            float g = l[e] * invs;
            sm[OFF_GATE + e * 128 + tid] = g;
            gw[e] = g;
        }
    }
    __syncthreads();

    // ---- experts: We1 (AF out) -> We2 (linear out) -> combine ----
    #pragma unroll 1
    for (int e = 0; e < NE; e++) {
        mma_pk<KS_E1, NT_E1, H1_, true, false, true>(
            sm + OFF_XP, g_pWe1 + (size_t)e * SZ_PWE1, be1 + e * H1_,
            sm + OFF_UN, warp, lane);
        __syncthreads();
        mma_pk<KS_E2, NT_E2, H2_, true, false, false>(
            sm + OFF_UN, g_pWe2 + (size_t)e * SZ_PWE2, be2 + e * H2_,
            sm + OFF_H2, warp, lane);
        __syncthreads();
        gemm_combine(sm + OFF_H2, We3 + (size_t)e * H2_ * DOUT, be3 + e * DOUT,
                     sm + OFF_GATE + e * 128, sm + OFF_ACC, tr, tc);
        // no barrier: combine reads H2/GATE, writes ACC; next We1 writes UN only,
        // and the barrier after it orders everything else.
    }
    __syncthreads();

    // ---- output LayerNorm over 8 dims, write out ----
    if (tid < MTILE) {
        float y[8];
        float s = 0.f;
        #pragma unroll
        for (int e = 0; e < DOUT; e++) { y[e] = sm[OFF_ACC + e * 128 + tid]; s += y[e]; }
        const float m = s * 0.125f;
        float var = 0.f;
        #pragma unroll
        for (int e = 0; e < DOUT; e++) { float d = y[e] - m; var += d * d; }
        var *= 0.125f;
        const float inv = rsqrtf(var + EPS);
        float* op = out + (size_t)(row0 + tid) * 8;
        #pragma unroll
        for (int e = 0; e < DOUT; e++)
            op[e] = (y[e] - m) * inv * ln_out_g[e] + ln_out_b[e];
    }
}

extern "C" void kernel_launch(void* const* d_in, const int* in_sizes, int n_in,
                              void* d_out, int out_size)
{
    const float* x       = (const float*)d_in[0];
    const float* ln_in_g = (const float*)d_in[1];
    const float* ln_in_b = (const float*)d_in[2];
    const float* Wp      = (const float*)d_in[3];
    const float* bp      = (const float*)d_in[4];
    const float* Wg1     = (const float*)d_in[5];
    const float* bg1     = (const float*)d_in[6];
    const float* Wg2     = (const float*)d_in[7];
    const float* bg2     = (const float*)d_in[8];
    const float* Wg3     = (const float*)d_in[9];
    const float* bg3     = (const float*)d_in[10];
    const float* We1     = (const float*)d_in[11];
    const float* be1     = (const float*)d_in[12];
    const float* We2     = (const float*)d_in[13];
    const float* be2     = (const float*)d_in[14];
    const float* We3     = (const float*)d_in[15];
    const float* be3     = (const float*)d_in[16];
    const float* ln_out_g= (const float*)d_in[17];
    const float* ln_out_b= (const float*)d_in[18];
    float* out = (float*)d_out;

    pack_kernel<<<(PACK_TOTAL + 255) / 256, 256>>>(Wp, Wg1, We1, We2);

    const size_t smem = SMEM_FLOATS * sizeof(float);
    cudaFuncSetAttribute(moe_fused_kernel,
                         cudaFuncAttributeMaxDynamicSharedMemorySize, (int)smem);

    moe_fused_kernel<<<B_ / MTILE, NTHREADS, smem>>>(
        x, ln_in_g, ln_in_b, bp, bg1, Wg2, bg2, Wg3, bg3,
        be1, be2, We3, be3, ln_out_g, ln_out_b, out);
}

// round 13
// speedup vs baseline: 2.4471x; 1.0302x over previous
#include <cuda_runtime.h>
#include <math.h>
#include <stdint.h>

// Problem dims
#define B_    262144
#define DIN   153
#define DOUT  8
#define NE    8
#define H1_   128
#define H2_   64
#define GH_   64
#define GH2_  32
#define EPS   1e-5f

#define MTILE 128
#define NTHREADS 512

// k-step / n-tile counts
#define KS_P   20   // Wp:  K=153 -> 20 k-steps
#define NT_P   20   // Wp:  N=153 (padded to 160)
#define KS_G1  20   // Wg1: K=153
#define NT_G1  8    // Wg1: N=64
#define KS_E1  20   // We1: K=153
#define NT_E1P 32   // We1 pair-merged: N=256
#define KS_E2  16   // We2: K=128
#define NT_E2  8    // We2: N=64

// ---- smem layout (floats) ----
// AF buffer per k-step: 4 rg x 2 half x 32 lanes x 4 floats = 1024
#define OFF_XP    0                        // x_norm -> x_proj in-place AF [20 ks] (20480)
#define OFF_H1E0  (OFF_XP + KS_P*1024)     // h1 expert-even AF [16 ks] (16384)
#define OFF_H1E1  (OFF_H1E0 + 16*1024)     // h1 expert-odd  AF [16 ks] (16384)
#define OFF_G1    OFF_H1E0                 // g1 linear [64][128] (aliases h1_e0, pre-experts)
#define OFF_G2    (OFF_H1E0 + 64*128)      // g2 linear [32][128]
#define OFF_H2    OFF_H1E0                 // h2 linear [64][128] (aliases h1_e0, sync-epi)
#define OFF_GATE  (OFF_H1E1 + 16*1024)     // gate [8][128]
#define OFF_ACC   (OFF_GATE + 8*128)       // acc  [8][128]
#define SMEM_FLOATS (OFF_ACC + 8*128)      // 55296 floats = 221,184 B

// ---- packed-weight global scratch ----
// frag (ks, nt) = 64 floats; lane l slot: [2l]=b0, [2l+1]=b1
// lane l: tig=l&3, gid=l>>2; b0 = W[(ks*8+tig)*N + nt*8+gid], b1 = +4 k-rows
#define SZ_PWP   (KS_P*NT_P*64)
#define SZ_PWG1  (KS_G1*NT_G1*64)
#define SZ_PWE1P (KS_E1*NT_E1P*64)        // per expert PAIR
#define SZ_PWE2  (KS_E2*NT_E2*64)
__device__ float g_pWp  [SZ_PWP];
__device__ float g_pWg1 [SZ_PWG1];
__device__ float g_pWe1p[(NE/2)*SZ_PWE1P];
__device__ float g_pWe2 [NE*SZ_PWE2];
#define PACK_TOTAL (SZ_PWP + SZ_PWG1 + (NE/2)*SZ_PWE1P + NE*SZ_PWE2)

__device__ __forceinline__ float pack_elem(const float* __restrict__ W,
                                           int K, int N, int NT, int rel)
{
    int ks    = rel / (NT * 64);
    int r     = rel % (NT * 64);
    int nt    = r / 64;
    int f     = r % 64;
    int lane  = f >> 1;
    int which = f & 1;
    int tig   = lane & 3;
    int gid   = lane >> 2;
    int k = ks * 8 + which * 4 + tig;
    int n = nt * 8 + gid;
    return (k < K && n < N) ? W[(size_t)k * N + n] : 0.f;
}

__global__ void pack_kernel(const float* __restrict__ Wp,
                            const float* __restrict__ Wg1,
                            const float* __restrict__ We1,
                            const float* __restrict__ We2)
{
    int idx = blockIdx.x * blockDim.x + threadIdx.x;
    if (idx >= PACK_TOTAL) return;
    if (idx < SZ_PWP) { g_pWp[idx] = pack_elem(Wp, DIN, DIN, NT_P, idx); return; }
    idx -= SZ_PWP;
    if (idx < SZ_PWG1) { g_pWg1[idx] = pack_elem(Wg1, DIN, GH_, NT_G1, idx); return; }
    idx -= SZ_PWG1;
    if (idx < (NE/2) * SZ_PWE1P) {
        int p = idx / SZ_PWE1P, rel = idx % SZ_PWE1P;
        // pair-merged We1: nt<16 -> expert 2p, nt>=16 -> expert 2p+1
        int ks = rel / (NT_E1P * 64);
        int r  = rel % (NT_E1P * 64);
        int nt = r / 64;
        int f  = r % 64;
        int lane = f >> 1, which = f & 1;
        int tig = lane & 3, gid = lane >> 2;
        int e  = 2 * p + (nt >= 16 ? 1 : 0);
        int n  = (nt & 15) * 8 + gid;
        int k  = ks * 8 + which * 4 + tig;
        const float* W = We1 + (size_t)e * DIN * H1_;
        g_pWe1p[idx] = (k < DIN) ? W[(size_t)k * H1_ + n] : 0.f;
        return;
    }
    idx -= (NE/2) * SZ_PWE1P;
    {
        int e = idx / SZ_PWE2, rel = idx % SZ_PWE2;
        g_pWe2[idx] = pack_elem(We2 + (size_t)e * H1_ * H2_, H1_, H2_, NT_E2, rel);
    }
}

// ---- AF addressing: value (k, r) ----
__device__ __forceinline__ int af_idx(int k, int r) {
    int ks = k >> 3, tigc = k & 3, kbit = (k >> 2) & 1;
    int rg = r >> 5, half = (r >> 4) & 1, gidc = r & 7, rbit = (r >> 3) & 1;
    return ((((ks * 4 + rg) * 2 + half) * 32 + gidc * 4 + tigc) << 2) + kbit * 2 + rbit;
}

// ---- packed f32x2 helpers ----
__device__ __forceinline__ uint64_t fma2(uint64_t a, uint64_t b, uint64_t c) {
    uint64_t d;
    asm("fma.rn.f32x2 %0, %1, %2, %3;" : "=l"(d) : "l"(a), "l"(b), "l"(c));
    return d;
}
__device__ __forceinline__ uint64_t add2(uint64_t a, uint64_t b) {
    uint64_t d;
    asm("add.rn.f32x2 %0, %1, %2;" : "=l"(d) : "l"(a), "l"(b));
    return d;
}
__device__ __forceinline__ uint64_t dup2(float w) {
    uint64_t d;
    asm("mov.b64 %0, {%1, %1};" : "=l"(d) : "f"(w));
    return d;
}
__device__ __forceinline__ void unpack2(uint64_t v, float& lo, float& hi) {
    asm("mov.b64 {%0, %1}, %2;" : "=f"(lo), "=f"(hi) : "l"(v));
}
__device__ __forceinline__ float tf32r(float x) {
    uint32_t u;
    asm("cvt.rna.tf32.f32 %0, %1;" : "=r"(u) : "f"(x));
    return __uint_as_float(u);
}

// ---- warp-level tf32 MMA m16n8k8 ----
__device__ __forceinline__ void mma8(float* d,
                                     uint32_t a0, uint32_t a1, uint32_t a2, uint32_t a3,
                                     uint32_t b0, uint32_t b1) {
    asm volatile(
        "mma.sync.aligned.m16n8k8.row.col.f32.tf32.tf32.f32 "
        "{%0,%1,%2,%3},{%4,%5,%6,%7},{%8,%9},{%0,%1,%2,%3};"
        : "+f"(d[0]), "+f"(d[1]), "+f"(d[2]), "+f"(d[3])
        : "r"(a0), "r"(a1), "r"(a2), "r"(a3), "r"(b0), "r"(b1));
}

// Tensor-core GEMM: AF A (LDS.128), packed B (LDG.64).
// SYNCEPI: barrier between mainloop and epilogue (enables in-place / aliased out).
template<int KS, int NT, int N, bool RELU, bool RESID, bool AFOUT, bool SYNCEPI>
__device__ __forceinline__ void mma_pk(const float* __restrict__ Aaf,
                                       const float* __restrict__ pk,
                                       const float* __restrict__ bias,
                                       float* __restrict__ Ot,
                                       int warp, int lane)
{
    constexpr int NTW = NT / 4;
    const int rg  = warp & 3;
    const int cg  = warp >> 2;
    const int gid = lane >> 2;
    const int tig = lane & 3;

    float acc[NTW][2][4];
    #pragma unroll
    for (int i = 0; i < NTW; i++)
        #pragma unroll
        for (int m = 0; m < 2; m++)
            #pragma unroll
            for (int q = 0; q < 4; q++) acc[i][m][q] = 0.f;

    const float4* __restrict__ afb = reinterpret_cast<const float4*>(Aaf);
    const float2* __restrict__ pb0 = reinterpret_cast<const float2*>(pk) + cg * 32 + lane;

    #pragma unroll 2
    for (int ks = 0; ks < KS; ks++) {
        const float4* ap = afb + ((ks * 4 + rg) * 2) * 32 + lane;
        float4 A = ap[0];
        float4 C = ap[32];
        const float2* pb = pb0 + ks * (NT * 32);
        #pragma unroll
        for (int i = 0; i < NTW; i++) {
            float2 b = pb[i * 128];
            uint32_t b0 = __float_as_uint(b.x), b1 = __float_as_uint(b.y);
            mma8(acc[i][0], __float_as_uint(A.x), __float_as_uint(A.y),
                            __float_as_uint(A.z), __float_as_uint(A.w), b0, b1);
            mma8(acc[i][1], __float_as_uint(C.x), __float_as_uint(C.y),
                            __float_as_uint(C.z), __float_as_uint(C.w), b0, b1);
        }
    }

    if (SYNCEPI) __syncthreads();

    #pragma unroll
    for (int i = 0; i < NTW; i++) {
        const int nt = cg + 4 * i;
        #pragma unroll
        for (int m = 0; m < 2; m++) {
            const int rl = rg * 32 + gid + m * 16;
            const int rh = rl + 8;
            #pragma unroll
            for (int h = 0; h < 2; h++) {
                const int col = nt * 8 + tig * 2 + h;
                if ((N % 8 == 0) || (col < N)) {
                    const float b = bias[col];
                    float v_lo = acc[i][m][h]     + b;
                    float v_hi = acc[i][m][2 + h] + b;
                    if (RELU) { v_lo = fmaxf(v_lo, 0.f); v_hi = fmaxf(v_hi, 0.f); }
                    if (RESID) {
                        v_lo += Aaf[af_idx(col, rl)];
                        v_hi += Aaf[af_idx(col, rh)];
                    }
                    if (AFOUT) {
                        Ot[af_idx(col, rl)] = tf32r(v_lo);
                        Ot[af_idx(col, rh)] = tf32r(v_hi);
                    } else {
                        Ot[col * 128 + rl] = v_lo;
                        Ot[col * 128 + rh] = v_hi;
                    }
                }
            }
        }
    }
}

// We1 pair-merged GEMM: A=XP, N=256 (cols 0..127 -> h1_e0, 128..255 -> h1_e1).
// SYNCEPI barrier also orders the preceding combine's H2 reads before h1 writes.
__device__ __forceinline__ void mma_we1pair(const float* __restrict__ Aaf,
                                            const float* __restrict__ pk,
                                            const float* __restrict__ bias, // be1 for 2 experts, 256
                                            float* __restrict__ h1e0,
                                            float* __restrict__ h1e1,
                                            int warp, int lane)
{
    constexpr int NTW = NT_E1P / 4;   // 8
    const int rg  = warp & 3;
    const int cg  = warp >> 2;
    const int gid = lane >> 2;
    const int tig = lane & 3;

    float acc[NTW][2][4];
    #pragma unroll
    for (int i = 0; i < NTW; i++)
        #pragma unroll
        for (int m = 0; m < 2; m++)
            #pragma unroll
            for (int q = 0; q < 4; q++) acc[i][m][q] = 0.f;

    const float4* __restrict__ afb = reinterpret_cast<const float4*>(Aaf);
    const float2* __restrict__ pb0 = reinterpret_cast<const float2*>(pk) + cg * 32 + lane;

    #pragma unroll 2
    for (int ks = 0; ks < KS_E1; ks++) {
        const float4* ap = afb + ((ks * 4 + rg) * 2) * 32 + lane;
        float4 A = ap[0];
        float4 C = ap[32];
        const float2* pb = pb0 + ks * (NT_E1P * 32);
        #pragma unroll
        for (int i = 0; i < NTW; i++) {
            float2 b = pb[i * 128];
            uint32_t b0 = __float_as_uint(b.x), b1 = __float_as_uint(b.y);
            mma8(acc[i][0], __float_as_uint(A.x), __float_as_uint(A.y),
                            __float_as_uint(A.z), __float_as_uint(A.w), b0, b1);
            mma8(acc[i][1], __float_as_uint(C.x), __float_as_uint(C.y),
                            __float_as_uint(C.z), __float_as_uint(C.w), b0, b1);
        }
    }

    __syncthreads();

    #pragma unroll
    for (int i = 0; i < NTW; i++) {
        const int nt = cg + 4 * i;
        float* __restrict__ Ot = (nt >= 16) ? h1e1 : h1e0;
        const int ntl = nt & 15;
        #pragma unroll
        for (int m = 0; m < 2; m++) {
            const int rl = rg * 32 + gid + m * 16;
            const int rh = rl + 8;
            #pragma unroll
            for (int h = 0; h < 2; h++) {
                const int col = nt * 8 + tig * 2 + h;       // 0..255 (bias idx)
                const int cc  = ntl * 8 + tig * 2 + h;      // 0..127 (local col)
                const float b = bias[col];
                float v_lo = fmaxf(acc[i][m][h]     + b, 0.f);
                float v_hi = fmaxf(acc[i][m][2 + h] + b, 0.f);
                Ot[af_idx(cc, rl)] = tf32r(v_lo);
                Ot[af_idx(cc, rh)] = tf32r(v_hi);
            }
        }
    }
}

// Scalar FFMA2 GEMM (small gating layers, fp32), linear layouts stride 128
template<int K, int N, bool RELU>
__device__ __forceinline__ void gemmT(const float* __restrict__ As,
                                      const float* __restrict__ W,
                                      const float* __restrict__ bias,
                                      float* __restrict__ Ot,
                                      int tr, int tc)
{
    const int r0 = tr * 8;
    uint64_t acc[4][4];
    #pragma unroll
    for (int j = 0; j < 4; j++)
        #pragma unroll
        for (int q = 0; q < 4; q++) acc[j][q] = 0ull;

    const float* __restrict__ Wc[4];
    bool ok[4];
    #pragma unroll
    for (int j = 0; j < 4; j++) {
        if (32 * j < N) {
            int col = 32 * j + tc;
            ok[j] = (col < N);
            Wc[j] = W + (ok[j] ? col : 0);
        }
    }
    #pragma unroll 4
    for (int k = 0; k < K; k++) {
        const float* ap = As + k * 128 + r0;
        ulonglong2 A0 = *(const ulonglong2*)(ap);
        ulonglong2 A1 = *(const ulonglong2*)(ap + 4);
        #pragma unroll
        for (int j = 0; j < 4; j++) {
            if (32 * j < N) {
                uint64_t wd = dup2(Wc[j][(size_t)k * N]);
                acc[j][0] = fma2(A0.x, wd, acc[j][0]);
                acc[j][1] = fma2(A0.y, wd, acc[j][1]);
                acc[j][2] = fma2(A1.x, wd, acc[j][2]);
                acc[j][3] = fma2(A1.y, wd, acc[j][3]);
            }
        }
    }
    #pragma unroll
    for (int j = 0; j < 4; j++) {
        if (32 * j < N) {
            int col = 32 * j + tc;
            if (ok[j]) {
                const float b = bias[col];
                float* op = Ot + col * 128 + r0;
                #pragma unroll
                for (int q = 0; q < 4; q++) {
                    float lo, hi;
                    unpack2(acc[j][q], lo, hi);
                    float v0 = lo + b, v1 = hi + b;
                    if (RELU) { v0 = fmaxf(v0, 0.f); v1 = fmaxf(v1, 0.f); }
                    op[2 * q]     = v0;
                    op[2 * q + 1] = v1;
                }
            }
        }
    }
}

// Expert output GEMM (K=64, N=8) fused with gating-weighted accumulate (h2 linear).
__device__ __forceinline__ void gemm_combine(const float* __restrict__ As,
                                             const float* __restrict__ W,
                                             const float* __restrict__ bias,
                                             const float* __restrict__ gate,
                                             float* __restrict__ accT,
                                             int tr, int tc)
{
    const int r0  = tr * 8;
    const int col = tc & 7;
    const int k0  = (tc >> 3) * 16;
    uint64_t acc[4] = {0ull, 0ull, 0ull, 0ull};
    const float* __restrict__ Wc = W + k0 * 8 + col;
    #pragma unroll 4
    for (int k = 0; k < 16; k++) {
        const float* ap = As + (k0 + k) * 128 + r0;
        ulonglong2 A0 = *(const ulonglong2*)(ap);
        ulonglong2 A1 = *(const ulonglong2*)(ap + 4);
        uint64_t wd = dup2(Wc[k * 8]);
        acc[0] = fma2(A0.x, wd, acc[0]);
        acc[1] = fma2(A0.y, wd, acc[1]);
        acc[2] = fma2(A1.x, wd, acc[2]);
        acc[3] = fma2(A1.y, wd, acc[3]);
    }
    #pragma unroll
    for (int q = 0; q < 4; q++) {
        double o16 = __shfl_down_sync(0xFFFFFFFFu,
                                      __longlong_as_double((long long)acc[q]), 16);
        acc[q] = add2(acc[q], (uint64_t)__double_as_longlong(o16));
        double o8 = __shfl_down_sync(0xFFFFFFFFu,
                                     __longlong_as_double((long long)acc[q]), 8);
        acc[q] = add2(acc[q], (uint64_t)__double_as_longlong(o8));
    }
    if (tc < 8) {
        const float b = bias[col];
        float* ap = accT + col * 128 + r0;
        #pragma unroll
        for (int q = 0; q < 4; q++) {
            float lo, hi;
            unpack2(acc[q], lo, hi);
            ap[2 * q]     += gate[r0 + 2 * q]     * (lo + b);
            ap[2 * q + 1] += gate[r0 + 2 * q + 1] * (hi + b);
        }
    }
}

__global__ __launch_bounds__(NTHREADS, 1)
void moe_fused_kernel(const float* __restrict__ x,
                      const float* __restrict__ ln_in_g, const float* __restrict__ ln_in_b,
                      const float* __restrict__ bp,
                      const float* __restrict__ bg1,
                      const float* __restrict__ Wg2, const float* __restrict__ bg2,
                      const float* __restrict__ Wg3, const float* __restrict__ bg3,
                      const float* __restrict__ be1,
                      const float* __restrict__ be2,
                      const float* __restrict__ We3, const float* __restrict__ be3,
                      const float* __restrict__ ln_out_g, const float* __restrict__ ln_out_b,
                      float* __restrict__ out)
{
    extern __shared__ float sm[];
    const int tid  = threadIdx.x;
    const int tr   = tid >> 5, tc = tid & 31;
    const int warp = tid >> 5, lane = tid & 31;
    const int row0 = blockIdx.x * MTILE;

    // zero ACC and the pad k-step block of XP (k=152..159 slots), then barrier
    // before LN writes into the same block (fixes R12 latent race).
    for (int i = tid; i < 8 * 128; i += NTHREADS) sm[OFF_ACC + i] = 0.f;
    for (int i = tid; i < 1024; i += NTHREADS)
        sm[OFF_XP + (KS_P - 1) * 1024 + i] = 0.f;
    __syncthreads();

    // ---- input LayerNorm -> XP (AF, tf32-rounded) ----
    for (int rr = warp; rr < MTILE; rr += 16) {
        const float* xr = x + (size_t)(row0 + rr) * DIN;
        float v[5];
        float s = 0.f, ss = 0.f;
        #pragma unroll
        for (int i = 0; i < 5; i++) {
            int k = i * 32 + lane;
            float val = (k < DIN) ? xr[k] : 0.f;
            v[i] = val; s += val; ss += val * val;
        }
        #pragma unroll
        for (int o = 16; o > 0; o >>= 1) {
            s  += __shfl_xor_sync(0xFFFFFFFFu, s,  o);
            ss += __shfl_xor_sync(0xFFFFFFFFu, ss, o);
        }
        const float m   = s * (1.f / DIN);
        const float var = ss * (1.f / DIN) - m * m;
        const float inv = rsqrtf(var + EPS);
        #pragma unroll
        for (int i = 0; i < 5; i++) {
            int k = i * 32 + lane;
            if (k < DIN)
                sm[OFF_XP + af_idx(k, rr)] =
                    tf32r((v[i] - m) * inv * ln_in_g[k] + ln_in_b[k]);
        }
    }
    __syncthreads();

    // ---- x_proj = relu(x_norm @ Wp + bp) + x_norm  (IN-PLACE on XP) ----
    mma_pk<KS_P, NT_P, DIN, true, true, true, true>(sm + OFF_XP, g_pWp, bp,
                                                    sm + OFF_XP, warp, lane);
    __syncthreads();

    // ---- gating: g1 tensor (linear out), g2/g3 scalar ----
    mma_pk<KS_G1, NT_G1, GH_, true, false, false, false>(sm + OFF_XP, g_pWg1, bg1,
                                                         sm + OFF_G1, warp, lane);
    __syncthreads();
    gemmT<GH_, GH2_, true>(sm + OFF_G1, Wg2, bg2, sm + OFF_G2, tr, tc);
    __syncthreads();
    gemmT<GH2_, 8, false>(sm + OFF_G2, Wg3, bg3, sm + OFF_GATE, tr, tc);
    __syncthreads();

    // ---- softmax over experts, write gating output ----
    if (tid < MTILE) {
        float l[8];
        float mx = -INFINITY;
        #pragma unroll
        for (int e = 0; e < NE; e++) { l[e] = sm[OFF_GATE + e * 128 + tid]; mx = fmaxf(mx, l[e]); }
        float s = 0.f;
        #pragma unroll
        for (int e = 0; e < NE; e++) { l[e] = expf(l[e] - mx); s += l[e]; }
        const float invs = 1.f / s;
        float* gw = out + (size_t)B_ * 8 + (size_t)(row0 + tid) * 8;
        #pragma unroll
        for (int e = 0; e < NE; e++) {
            float g = l[e] * invs;
            sm[OFF_GATE + e * 128 + tid] = g;
            gw[e] = g;
        }
    }
    __syncthreads();

    // ---- experts: 4 pair-passes. We1 merged (N=256) -> We2 per expert -> combine ----
    #pragma unroll 1
    for (int p = 0; p < NE / 2; p++) {
        // We1 pair: internal pre-epilogue barrier also orders the previous
        // combine's H2 reads (H2 aliases h1_e0) before h1 writes.
        mma_we1pair(sm + OFF_XP, g_pWe1p + (size_t)p * SZ_PWE1P,
                    be1 + 2 * p * H1_, sm + OFF_H1E0, sm + OFF_H1E1, warp, lane);
        __syncthreads();

        #pragma unroll 1
        for (int q = 0; q < 2; q++) {
            const int e = 2 * p + q;
            const float* h1 = sm + (q ? OFF_H1E1 : OFF_H1E0);
            // We2: SYNCEPI because H2 output aliases h1_e0 (A of q=0 pass), and
            // orders the previous combine's H2 reads before these H2 writes.
            mma_pk<KS_E2, NT_E2, H2_, true, false, false, true>(
                h1, g_pWe2 + (size_t)e * SZ_PWE2, be2 + e * H2_,
                sm + OFF_H2, warp, lane);
            __syncthreads();
            gemm_combine(sm + OFF_H2, We3 + (size_t)e * H2_ * DOUT, be3 + e * DOUT,
                         sm + OFF_GATE + e * 128, sm + OFF_ACC, tr, tc);
            __syncthreads();
        }
    }

    // ---- output LayerNorm over 8 dims, write out ----
    if (tid < MTILE) {
        float y[8];
        float s = 0.f;
        #pragma unroll
        for (int e = 0; e < DOUT; e++) { y[e] = sm[OFF_ACC + e * 128 + tid]; s += y[e]; }
        const float m = s * 0.125f;
        float var = 0.f;
        #pragma unroll
        for (int e = 0; e < DOUT; e++) { float d = y[e] - m; var += d * d; }
        var *= 0.125f;
        const float inv = rsqrtf(var + EPS);
        float* op = out + (size_t)(row0 + tid) * 8;
        #pragma unroll
        for (int e = 0; e < DOUT; e++)
            op[e] = (y[e] - m) * inv * ln_out_g[e] + ln_out_b[e];
    }
}

extern "C" void kernel_launch(void* const* d_in, const int* in_sizes, int n_in,
                              void* d_out, int out_size)
{
    const float* x       = (const float*)d_in[0];
    const float* ln_in_g = (const float*)d_in[1];
    const float* ln_in_b = (const float*)d_in[2];
    const float* Wp      = (const float*)d_in[3];
    const float* bp      = (const float*)d_in[4];
    const float* Wg1     = (const float*)d_in[5];
    const float* bg1     = (const float*)d_in[6];
    const float* Wg2     = (const float*)d_in[7];
    const float* bg2     = (const float*)d_in[8];
    const float* Wg3     = (const float*)d_in[9];
    const float* bg3     = (const float*)d_in[10];
    const float* We1     = (const float*)d_in[11];
    const float* be1     = (const float*)d_in[12];
    const float* We2     = (const float*)d_in[13];
    const float* be2     = (const float*)d_in[14];
    const float* We3     = (const float*)d_in[15];
    const float* be3     = (const float*)d_in[16];
    const float* ln_out_g= (const float*)d_in[17];
    const float* ln_out_b= (const float*)d_in[18];
    float* out = (float*)d_out;

    pack_kernel<<<(PACK_TOTAL + 255) / 256, 256>>>(Wp, Wg1, We1, We2);

    const size_t smem = SMEM_FLOATS * sizeof(float);
    cudaFuncSetAttribute(moe_fused_kernel,
                         cudaFuncAttributeMaxDynamicSharedMemorySize, (int)smem);

    moe_fused_kernel<<<B_ / MTILE, NTHREADS, smem>>>(
        x, ln_in_g, ln_in_b, bp, bg1, Wg2, bg2, Wg3, bg3,
        be1, be2, We3, be3, ln_out_g, ln_out_b, out);
}

// round 15
// speedup vs baseline: 2.5542x; 1.0438x over previous
#include <cuda_runtime.h>
#include <math.h>
#include <stdint.h>

// Problem dims
#define B_    262144
#define DIN   153
#define DOUT  8
#define NE    8
#define H1_   128
#define H2_   64
#define GH_   64
#define GH2_  32
#define EPS   1e-5f

#define MTILE 128
#define NTHREADS 512

// k-step / n-tile counts
#define KS_P   20
#define NT_P   20
#define KS_G1  20
#define NT_G1  8
#define KS_E1  20
#define NT_E1P 32
#define KS_E2  16
#define NT_E2  8

// ---- smem layout (floats) ----
#define OFF_XP    0                        // x_norm -> x_proj in-place AF (20480)
#define OFF_H1E0  (OFF_XP + KS_P*1024)     // h1 expert-even AF [16 ks] (16384)
#define OFF_H1E1  (OFF_H1E0 + 16*1024)     // h1 expert-odd  AF (16384)
#define OFF_G1    OFF_H1E0                 // g1 linear [64][128] (alias, pre-experts)
#define OFF_G2    (OFF_H1E0 + 64*128)      // g2 linear [32][128]
#define OFF_H2P   OFF_H1E0                 // H2 pair [2][64][128] (alias, sync-epi)
#define OFF_GATE  (OFF_H1E1 + 16*1024)     // gate [8][128]
#define OFF_ACC   (OFF_GATE + 8*128)       // acc  [2][8][128]
#define SMEM_FLOATS (OFF_ACC + 2*8*128)    // 56320 floats = 225,280 B

// ---- packed-weight global scratch ----
#define SZ_PWP   (KS_P*NT_P*64)
#define SZ_PWG1  (KS_G1*NT_G1*64)
#define SZ_PWE1P (KS_E1*NT_E1P*64)
#define SZ_PWE2  (KS_E2*NT_E2*64)
__device__ float g_pWp  [SZ_PWP];
__device__ float g_pWg1 [SZ_PWG1];
__device__ float g_pWe1p[(NE/2)*SZ_PWE1P];
__device__ float g_pWe2 [NE*SZ_PWE2];
#define PACK_TOTAL (SZ_PWP + SZ_PWG1 + (NE/2)*SZ_PWE1P + NE*SZ_PWE2)

__device__ __forceinline__ float pack_elem(const float* __restrict__ W,
                                           int K, int N, int NT, int rel)
{
    int ks    = rel / (NT * 64);
    int r     = rel % (NT * 64);
    int nt    = r / 64;
    int f     = r % 64;
    int lane  = f >> 1;
    int which = f & 1;
    int tig   = lane & 3;
    int gid   = lane >> 2;
    int k = ks * 8 + which * 4 + tig;
    int n = nt * 8 + gid;
    return (k < K && n < N) ? W[(size_t)k * N + n] : 0.f;
}

__global__ void pack_kernel(const float* __restrict__ Wp,
                            const float* __restrict__ Wg1,
                            const float* __restrict__ We1,
                            const float* __restrict__ We2)
{
    int idx = blockIdx.x * blockDim.x + threadIdx.x;
    if (idx >= PACK_TOTAL) return;
    if (idx < SZ_PWP) { g_pWp[idx] = pack_elem(Wp, DIN, DIN, NT_P, idx); return; }
    idx -= SZ_PWP;
    if (idx < SZ_PWG1) { g_pWg1[idx] = pack_elem(Wg1, DIN, GH_, NT_G1, idx); return; }
    idx -= SZ_PWG1;
    if (idx < (NE/2) * SZ_PWE1P) {
        int p = idx / SZ_PWE1P, rel = idx % SZ_PWE1P;
        int ks = rel / (NT_E1P * 64);
        int r  = rel % (NT_E1P * 64);
        int nt = r / 64;
        int f  = r % 64;
        int lane = f >> 1, which = f & 1;
        int tig = lane & 3, gid = lane >> 2;
        int e  = 2 * p + (nt >= 16 ? 1 : 0);
        int n  = (nt & 15) * 8 + gid;
        int k  = ks * 8 + which * 4 + tig;
        const float* W = We1 + (size_t)e * DIN * H1_;
        g_pWe1p[idx] = (k < DIN) ? W[(size_t)k * H1_ + n] : 0.f;
        return;
    }
    idx -= (NE/2) * SZ_PWE1P;
    {
        int e = idx / SZ_PWE2, rel = idx % SZ_PWE2;
        g_pWe2[idx] = pack_elem(We2 + (size_t)e * H1_ * H2_, H1_, H2_, NT_E2, rel);
    }
}

// ---- AF addressing ----
__device__ __forceinline__ int af_idx(int k, int r) {
    int ks = k >> 3, tigc = k & 3, kbit = (k >> 2) & 1;
    int rg = r >> 5, half = (r >> 4) & 1, gidc = r & 7, rbit = (r >> 3) & 1;
    return ((((ks * 4 + rg) * 2 + half) * 32 + gidc * 4 + tigc) << 2) + kbit * 2 + rbit;
}

// ---- packed f32x2 helpers ----
__device__ __forceinline__ uint64_t fma2(uint64_t a, uint64_t b, uint64_t c) {
    uint64_t d;
    asm("fma.rn.f32x2 %0, %1, %2, %3;" : "=l"(d) : "l"(a), "l"(b), "l"(c));
    return d;
}
__device__ __forceinline__ uint64_t add2(uint64_t a, uint64_t b) {
    uint64_t d;
    asm("add.rn.f32x2 %0, %1, %2;" : "=l"(d) : "l"(a), "l"(b));
    return d;
}
__device__ __forceinline__ uint64_t dup2(float w) {
    uint64_t d;
    asm("mov.b64 %0, {%1, %1};" : "=l"(d) : "f"(w));
    return d;
}
__device__ __forceinline__ void unpack2(uint64_t v, float& lo, float& hi) {
    asm("mov.b64 {%0, %1}, %2;" : "=f"(lo), "=f"(hi) : "l"(v));
}
__device__ __forceinline__ float tf32r(float x) {
    uint32_t u;
    asm("cvt.rna.tf32.f32 %0, %1;" : "=r"(u) : "f"(x));
    return __uint_as_float(u);
}

// ---- warp-level tf32 MMA m16n8k8 ----
__device__ __forceinline__ void mma8(float* d,
                                     uint32_t a0, uint32_t a1, uint32_t a2, uint32_t a3,
                                     uint32_t b0, uint32_t b1) {
    asm volatile(
        "mma.sync.aligned.m16n8k8.row.col.f32.tf32.tf32.f32 "
        "{%0,%1,%2,%3},{%4,%5,%6,%7},{%8,%9},{%0,%1,%2,%3};"
        : "+f"(d[0]), "+f"(d[1]), "+f"(d[2]), "+f"(d[3])
        : "r"(a0), "r"(a1), "r"(a2), "r"(a3), "r"(b0), "r"(b1));
}

// ---- vectorized AF epilogue store: shfl-transpose + STS.128 ----
// v[h][p]: value for col = nt*8+tig*2+h, row = rg*32+m*16+gid+8p (bias/relu/guard
// already applied). Assembles the 16B AF group {(c,r),(c,r+8),(c+4,r),(c+4,r+8)}.
template<bool RESID>
__device__ __forceinline__ void epi_af_vec(const float v[2][2],
                                           float* __restrict__ Ot,
                                           const float* __restrict__ Ar,
                                           int nt, int rg, int m, int gid, int tig)
{
    float s00 = __shfl_xor_sync(0xFFFFFFFFu, v[0][0], 2);
    float s01 = __shfl_xor_sync(0xFFFFFFFFu, v[0][1], 2);
    float s10 = __shfl_xor_sync(0xFFFFFFFFu, v[1][0], 2);
    float s11 = __shfl_xor_sync(0xFFFFFFFFu, v[1][1], 2);
    float lo0, lo1, hi0, hi1;
    int tigc;
    if (tig < 2) { lo0 = v[0][0]; lo1 = v[0][1]; hi0 = s00; hi1 = s01; tigc = 2 * tig; }
    else         { lo0 = s10; lo1 = s11; hi0 = v[1][0]; hi1 = v[1][1]; tigc = 2 * (tig - 2) + 1; }
    const int f4 = ((nt * 4 + rg) * 2 + m) * 32 + gid * 4 + tigc;
    if (RESID) {
        float4 old = reinterpret_cast<const float4*>(Ar)[f4];
        lo0 += old.x; lo1 += old.y; hi0 += old.z; hi1 += old.w;
    }
    float4 o;
    o.x = tf32r(lo0); o.y = tf32r(lo1); o.z = tf32r(hi0); o.w = tf32r(hi1);
    reinterpret_cast<float4*>(Ot)[f4] = o;
}

// Tensor-core GEMM: AF A (LDS.128), packed B (LDG.64). 4 rg x 4 cg warps.
// AFOUT: vectorized AF epilogue; else linear [col*128+r]. SYNCEPI: barrier pre-epilogue.
template<int KS, int NT, int N, bool RELU, bool RESID, bool AFOUT, bool SYNCEPI>
__device__ __forceinline__ void mma_pk(const float* __restrict__ Aaf,
                                       const float* __restrict__ pk,
                                       const float* __restrict__ bias,
                                       float* __restrict__ Ot,
                                       int warp, int lane)
{
    constexpr int NTW = NT / 4;
    const int rg  = warp & 3;
    const int cg  = warp >> 2;
    const int gid = lane >> 2;
    const int tig = lane & 3;

    float acc[NTW][2][4];
    #pragma unroll
    for (int i = 0; i < NTW; i++)
        #pragma unroll
        for (int m = 0; m < 2; m++)
            #pragma unroll
            for (int q = 0; q < 4; q++) acc[i][m][q] = 0.f;

    const float4* __restrict__ afb = reinterpret_cast<const float4*>(Aaf);
    const float2* __restrict__ pb0 = reinterpret_cast<const float2*>(pk) + cg * 32 + lane;

    #pragma unroll 2
    for (int ks = 0; ks < KS; ks++) {
        const float4* ap = afb + ((ks * 4 + rg) * 2) * 32 + lane;
        float4 A = ap[0];
        float4 C = ap[32];
        const float2* pb = pb0 + ks * (NT * 32);
        #pragma unroll
        for (int i = 0; i < NTW; i++) {
            float2 b = pb[i * 128];
            uint32_t b0 = __float_as_uint(b.x), b1 = __float_as_uint(b.y);
            mma8(acc[i][0], __float_as_uint(A.x), __float_as_uint(A.y),
                            __float_as_uint(A.z), __float_as_uint(A.w), b0, b1);
            mma8(acc[i][1], __float_as_uint(C.x), __float_as_uint(C.y),
                            __float_as_uint(C.z), __float_as_uint(C.w), b0, b1);
        }
    }

    if (SYNCEPI) __syncthreads();

    #pragma unroll
    for (int i = 0; i < NTW; i++) {
        const int nt = cg + 4 * i;
        #pragma unroll
        for (int m = 0; m < 2; m++) {
            if (AFOUT) {
                float v[2][2];
                #pragma unroll
                for (int h = 0; h < 2; h++) {
                    const int col = nt * 8 + tig * 2 + h;
                    const bool ok = (N % 8 == 0) || (col < N);
                    const float b = ok ? bias[col] : 0.f;
                    float v0 = acc[i][m][h]     + b;
                    float v1 = acc[i][m][2 + h] + b;
                    if (RELU) { v0 = fmaxf(v0, 0.f); v1 = fmaxf(v1, 0.f); }
                    v[h][0] = ok ? v0 : 0.f;
                    v[h][1] = ok ? v1 : 0.f;
                }
                epi_af_vec<RESID>(v, Ot, Aaf, nt, rg, m, gid, tig);
            } else {
                const int rl = rg * 32 + gid + m * 16;
                const int rh = rl + 8;
                #pragma unroll
                for (int h = 0; h < 2; h++) {
                    const int col = nt * 8 + tig * 2 + h;
                    if ((N % 8 == 0) || (col < N)) {
                        const float b = bias[col];
                        float v0 = acc[i][m][h]     + b;
                        float v1 = acc[i][m][2 + h] + b;
                        if (RELU) { v0 = fmaxf(v0, 0.f); v1 = fmaxf(v1, 0.f); }
                        Ot[col * 128 + rl] = v0;
                        Ot[col * 128 + rh] = v1;
                    }
                }
            }
        }
    }
}

// We1 pair-merged GEMM: N=256 (nt<16 -> h1_e0, nt>=16 -> h1_e1), vectorized AF out.
__device__ __forceinline__ void mma_we1pair(const float* __restrict__ Aaf,
                                            const float* __restrict__ pk,
                                            const float* __restrict__ bias,
                                            float* __restrict__ h1e0,
                                            float* __restrict__ h1e1,
                                            int warp, int lane)
{
    constexpr int NTW = NT_E1P / 4;   // 8
    const int rg  = warp & 3;
    const int cg  = warp >> 2;
    const int gid = lane >> 2;
    const int tig = lane & 3;

    float acc[NTW][2][4];
    #pragma unroll
    for (int i = 0; i < NTW; i++)
        #pragma unroll
        for (int m = 0; m < 2; m++)
            #pragma unroll
            for (int q = 0; q < 4; q++) acc[i][m][q] = 0.f;

    const float4* __restrict__ afb = reinterpret_cast<const float4*>(Aaf);
    const float2* __restrict__ pb0 = reinterpret_cast<const float2*>(pk) + cg * 32 + lane;

    #pragma unroll 2
    for (int ks = 0; ks < KS_E1; ks++) {
        const float4* ap = afb + ((ks * 4 + rg) * 2) * 32 + lane;
        float4 A = ap[0];
        float4 C = ap[32];
        const float2* pb = pb0 + ks * (NT_E1P * 32);
        #pragma unroll
        for (int i = 0; i < NTW; i++) {
            float2 b = pb[i * 128];
            uint32_t b0 = __float_as_uint(b.x), b1 = __float_as_uint(b.y);
            mma8(acc[i][0], __float_as_uint(A.x), __float_as_uint(A.y),
                            __float_as_uint(A.z), __float_as_uint(A.w), b0, b1);
            mma8(acc[i][1], __float_as_uint(C.x), __float_as_uint(C.y),
                            __float_as_uint(C.z), __float_as_uint(C.w), b0, b1);
        }
    }

    __syncthreads();

    #pragma unroll
    for (int i = 0; i < NTW; i++) {
        const int nt  = cg + 4 * i;
        float* __restrict__ Ot = (nt >= 16) ? h1e1 : h1e0;
        const int ntl = nt & 15;
        #pragma unroll
        for (int m = 0; m < 2; m++) {
            float v[2][2];
            #pragma unroll
            for (int h = 0; h < 2; h++) {
                const int col = nt * 8 + tig * 2 + h;
                const float b = bias[col];
                v[h][0] = fmaxf(acc[i][m][h]     + b, 0.f);
                v[h][1] = fmaxf(acc[i][m][2 + h] + b, 0.f);
            }
            epi_af_vec<false>(v, Ot, Ot, ntl, rg, m, gid, tig);
        }
    }
}

// We2 pair-merged: warps 0-7 -> e0 (A=h1e0), 8-15 -> e1 (A=h1e1); linear H2 pair out.
__device__ __forceinline__ void mma_we2pair(const float* __restrict__ smbase,
                                            const float* __restrict__ pkPair, // e0 base
                                            const float* __restrict__ be2,    // global
                                            float* __restrict__ H2p,
                                            int pairIdx, int warp, int lane)
{
    const int q   = warp >> 3;
    const int w   = warp & 7;
    const int rg  = w & 3;
    const int cg  = w >> 2;        // 0-1
    const int gid = lane >> 2;
    const int tig = lane & 3;
    const int e   = 2 * pairIdx + q;

    const float* Aaf  = smbase + (q ? OFF_H1E1 : OFF_H1E0);
    const float* pk   = pkPair + (size_t)q * SZ_PWE2;
    const float* bias = be2 + e * H2_;

    float acc[4][2][4];
    #pragma unroll
    for (int i = 0; i < 4; i++)
        #pragma unroll
        for (int m = 0; m < 2; m++)
            #pragma unroll
            for (int t = 0; t < 4; t++) acc[i][m][t] = 0.f;

    const float4* __restrict__ afb = reinterpret_cast<const float4*>(Aaf);
    const float2* __restrict__ pb0 = reinterpret_cast<const float2*>(pk) + cg * 32 + lane;

    #pragma unroll 2
    for (int ks = 0; ks < KS_E2; ks++) {
        const float4* ap = afb + ((ks * 4 + rg) * 2) * 32 + lane;
        float4 A = ap[0];
        float4 C = ap[32];
        const float2* pb = pb0 + ks * (NT_E2 * 32);
        #pragma unroll
        for (int i = 0; i < 4; i++) {
            float2 b = pb[i * 64];     // nt = cg + 2*i
            uint32_t b0 = __float_as_uint(b.x), b1 = __float_as_uint(b.y);
            mma8(acc[i][0], __float_as_uint(A.x), __float_as_uint(A.y),
                            __float_as_uint(A.z), __float_as_uint(A.w), b0, b1);
            mma8(acc[i][1], __float_as_uint(C.x), __float_as_uint(C.y),
                            __float_as_uint(C.z), __float_as_uint(C.w), b0, b1);
        }
    }

    __syncthreads();   // all h1 reads done; H2p aliases h1e0 region

    float* __restrict__ Ot = H2p + q * (H2_ * 128);
    #pragma unroll
    for (int i = 0; i < 4; i++) {
        const int nt = cg + 2 * i;
        #pragma unroll
        for (int m = 0; m < 2; m++) {
            const int rl = rg * 32 + gid + m * 16;
            const int rh = rl + 8;
            #pragma unroll
            for (int h = 0; h < 2; h++) {
                const int col = nt * 8 + tig * 2 + h;
                const float b = bias[col];
                Ot[col * 128 + rl] = fmaxf(acc[i][m][h]     + b, 0.f);
                Ot[col * 128 + rh] = fmaxf(acc[i][m][2 + h] + b, 0.f);
            }
        }
    }
}

// Pair combine: warps 0-7 -> e0, 8-15 -> e1; 16 rows/warp, lanes k-quartered.
__device__ __forceinline__ void gemm_combine_pair(const float* __restrict__ H2p,
                                                  const float* __restrict__ We3,
                                                  const float* __restrict__ be3,
                                                  const float* __restrict__ gate,
                                                  float* __restrict__ accP,
                                                  int pairIdx, int warp, int lane)
{
    const int q   = warp >> 3;
    const int w   = warp & 7;
    const int e   = 2 * pairIdx + q;
    const int r0  = w * 16;
    const int col = lane & 7;
    const int kq  = lane >> 3;
    const float* As = H2p + q * (H2_ * 128);
    const float* Wc = We3 + (size_t)e * H2_ * DOUT + kq * 16 * 8 + col;

    uint64_t acc[8];
    #pragma unroll
    for (int j = 0; j < 8; j++) acc[j] = 0ull;

    #pragma unroll 4
    for (int k = 0; k < 16; k++) {
        const float* ap = As + (kq * 16 + k) * 128 + r0;
        ulonglong2 A0 = *(const ulonglong2*)(ap);
        ulonglong2 A1 = *(const ulonglong2*)(ap + 4);
        ulonglong2 A2 = *(const ulonglong2*)(ap + 8);
        ulonglong2 A3 = *(const ulonglong2*)(ap + 12);
        uint64_t wd = dup2(Wc[k * 8]);
        acc[0] = fma2(A0.x, wd, acc[0]); acc[1] = fma2(A0.y, wd, acc[1]);
        acc[2] = fma2(A1.x, wd, acc[2]); acc[3] = fma2(A1.y, wd, acc[3]);
        acc[4] = fma2(A2.x, wd, acc[4]); acc[5] = fma2(A2.y, wd, acc[5]);
        acc[6] = fma2(A3.x, wd, acc[6]); acc[7] = fma2(A3.y, wd, acc[7]);
    }
    #pragma unroll
    for (int j = 0; j < 8; j++) {
        double o16 = __shfl_down_sync(0xFFFFFFFFu,
                                      __longlong_as_double((long long)acc[j]), 16);
        acc[j] = add2(acc[j], (uint64_t)__double_as_longlong(o16));
        double o8 = __shfl_down_sync(0xFFFFFFFFu,
                                     __longlong_as_double((long long)acc[j]), 8);
        acc[j] = add2(acc[j], (uint64_t)__double_as_longlong(o8));
    }
    if (lane < 8) {
        const float b = be3[e * DOUT + col];
        const float* gr = gate + e * 128 + r0;
        float* ap = accP + q * 1024 + col * 128 + r0;
        #pragma unroll
        for (int j = 0; j < 8; j++) {
            float lo, hi;
            unpack2(acc[j], lo, hi);
            ap[2 * j]     += gr[2 * j]     * (lo + b);
            ap[2 * j + 1] += gr[2 * j + 1] * (hi + b);
        }
    }
}

// Scalar FFMA2 GEMM (small gating layers, fp32), linear layouts stride 128
template<int K, int N, bool RELU>
__device__ __forceinline__ void gemmT(const float* __restrict__ As,
                                      const float* __restrict__ W,
                                      const float* __restrict__ bias,
                                      float* __restrict__ Ot,
                                      int tr, int tc)
{
    const int r0 = tr * 8;
    uint64_t acc[4][4];
    #pragma unroll
    for (int j = 0; j < 4; j++)
        #pragma unroll
        for (int q = 0; q < 4; q++) acc[j][q] = 0ull;

    const float* __restrict__ Wc[4];
    bool ok[4];
    #pragma unroll
    for (int j = 0; j < 4; j++) {
        if (32 * j < N) {
            int col = 32 * j + tc;
            ok[j] = (col < N);
            Wc[j] = W + (ok[j] ? col : 0);
        }
    }
    #pragma unroll 4
    for (int k = 0; k < K; k++) {
        const float* ap = As + k * 128 + r0;
        ulonglong2 A0 = *(const ulonglong2*)(ap);
        ulonglong2 A1 = *(const ulonglong2*)(ap + 4);
        #pragma unroll
        for (int j = 0; j < 4; j++) {
            if (32 * j < N) {
                uint64_t wd = dup2(Wc[j][(size_t)k * N]);
                acc[j][0] = fma2(A0.x, wd, acc[j][0]);
                acc[j][1] = fma2(A0.y, wd, acc[j][1]);
                acc[j][2] = fma2(A1.x, wd, acc[j][2]);
                acc[j][3] = fma2(A1.y, wd, acc[j][3]);
            }
        }
    }
    #pragma unroll
    for (int j = 0; j < 4; j++) {
        if (32 * j < N) {
            int col = 32 * j + tc;
            if (ok[j]) {
                const float b = bias[col];
                float* op = Ot + col * 128 + r0;
                #pragma unroll
                for (int q = 0; q < 4; q++) {
                    float lo, hi;
                    unpack2(acc[j][q], lo, hi);
                    float v0 = lo + b, v1 = hi + b;
                    if (RELU) { v0 = fmaxf(v0, 0.f); v1 = fmaxf(v1, 0.f); }
                    op[2 * q]     = v0;
                    op[2 * q + 1] = v1;
                }
            }
        }
    }
}

__global__ __launch_bounds__(NTHREADS, 1)
void moe_fused_kernel(const float* __restrict__ x,
                      const float* __restrict__ ln_in_g, const float* __restrict__ ln_in_b,
                      const float* __restrict__ bp,
                      const float* __restrict__ bg1,
                      const float* __restrict__ Wg2, const float* __restrict__ bg2,
                      const float* __restrict__ Wg3, const float* __restrict__ bg3,
                      const float* __restrict__ be1,
                      const float* __restrict__ be2,
                      const float* __restrict__ We3, const float* __restrict__ be3,
                      const float* __restrict__ ln_out_g, const float* __restrict__ ln_out_b,
                      float* __restrict__ out)
{
    extern __shared__ float sm[];
    const int tid  = threadIdx.x;
    const int tr   = tid >> 5, tc = tid & 31;
    const int warp = tid >> 5, lane = tid & 31;
    const int row0 = blockIdx.x * MTILE;

    // zero both ACC buffers and the XP pad k-step (k=152..159 slots); barrier
    // before LN writes into the same k-step block.
    for (int i = tid; i < 2 * 8 * 128; i += NTHREADS) sm[OFF_ACC + i] = 0.f;
    for (int i = tid; i < 1024; i += NTHREADS)
        sm[OFF_XP + (KS_P - 1) * 1024 + i] = 0.f;
    __syncthreads();

    // ---- input LayerNorm -> XP (AF, tf32-rounded) ----
    for (int rr = warp; rr < MTILE; rr += 16) {
        const float* xr = x + (size_t)(row0 + rr) * DIN;
        float v[5];
        float s = 0.f, ss = 0.f;
        #pragma unroll
        for (int i = 0; i < 5; i++) {
            int k = i * 32 + lane;
            float val = (k < DIN) ? xr[k] : 0.f;
            v[i] = val; s += val; ss += val * val;
        }
        #pragma unroll
        for (int o = 16; o > 0; o >>= 1) {
            s  += __shfl_xor_sync(0xFFFFFFFFu, s,  o);
            ss += __shfl_xor_sync(0xFFFFFFFFu, ss, o);
        }
        const float m   = s * (1.f / DIN);
        const float var = ss * (1.f / DIN) - m * m;
        const float inv = rsqrtf(var + EPS);
        #pragma unroll
        for (int i = 0; i < 5; i++) {
            int k = i * 32 + lane;
            if (k < DIN)
                sm[OFF_XP + af_idx(k, rr)] =
                    tf32r((v[i] - m) * inv * ln_in_g[k] + ln_in_b[k]);
        }
    }
    __syncthreads();

    // ---- x_proj = relu(x_norm @ Wp + bp) + x_norm  (IN-PLACE, vec epi) ----
    mma_pk<KS_P, NT_P, DIN, true, true, true, true>(sm + OFF_XP, g_pWp, bp,
                                                    sm + OFF_XP, warp, lane);
    __syncthreads();

    // ---- gating: g1 tensor (linear out), g2/g3 scalar ----
    mma_pk<KS_G1, NT_G1, GH_, true, false, false, false>(sm + OFF_XP, g_pWg1, bg1,
                                                         sm + OFF_G1, warp, lane);
    __syncthreads();
    gemmT<GH_, GH2_, true>(sm + OFF_G1, Wg2, bg2, sm + OFF_G2, tr, tc);
    __syncthreads();
    gemmT<GH2_, 8, false>(sm + OFF_G2, Wg3, bg3, sm + OFF_GATE, tr, tc);
    __syncthreads();

    // ---- softmax over experts, write gating output ----
    if (tid < MTILE) {
        float l[8];
        float mx = -INFINITY;
        #pragma unroll
        for (int e = 0; e < NE; e++) { l[e] = sm[OFF_GATE + e * 128 + tid]; mx = fmaxf(mx, l[e]); }
        float s = 0.f;
        #pragma unroll
        for (int e = 0; e < NE; e++) { l[e] = expf(l[e] - mx); s += l[e]; }
        const float invs = 1.f / s;
        float* gw = out + (size_t)B_ * 8 + (size_t)(row0 + tid) * 8;
        #pragma unroll
        for (int e = 0; e < NE; e++) {
            float g = l[e] * invs;
            sm[OFF_GATE + e * 128 + tid] = g;
            gw[e] = g;
        }
    }
    __syncthreads();

    // ---- experts: 4 pair-passes, fully pair-parallel ----
    #pragma unroll 1
    for (int p = 0; p < NE / 2; p++) {
        mma_we1pair(sm + OFF_XP, g_pWe1p + (size_t)p * SZ_PWE1P,
                    be1 + 2 * p * H1_, sm + OFF_H1E0, sm + OFF_H1E1, warp, lane);
        __syncthreads();
        mma_we2pair(sm, g_pWe2 + (size_t)(2 * p) * SZ_PWE2, be2,
                    sm + OFF_H2P, p, warp, lane);
        __syncthreads();
        gemm_combine_pair(sm + OFF_H2P, We3, be3, sm + OFF_GATE,
                          sm + OFF_ACC, p, warp, lane);
        __syncthreads();
    }

    // ---- output LayerNorm over 8 dims (sum both ACC buffers), write out ----
    if (tid < MTILE) {
        float y[8];
        float s = 0.f;
        #pragma unroll
        for (int e = 0; e < DOUT; e++) {
            y[e] = sm[OFF_ACC + e * 128 + tid] + sm[OFF_ACC + 1024 + e * 128 + tid];
            s += y[e];
        }
        const float m = s * 0.125f;
        float var = 0.f;
        #pragma unroll
        for (int e = 0; e < DOUT; e++) { float d = y[e] - m; var += d * d; }
        var *= 0.125f;
        const float inv = rsqrtf(var + EPS);
        float* op = out + (size_t)(row0 + tid) * 8;
        #pragma unroll
        for (int e = 0; e < DOUT; e++)
            op[e] = (y[e] - m) * inv * ln_out_g[e] + ln_out_b[e];
    }
}

extern "C" void kernel_launch(void* const* d_in, const int* in_sizes, int n_in,
                              void* d_out, int out_size)
{
    const float* x       = (const float*)d_in[0];
    const float* ln_in_g = (const float*)d_in[1];
    const float* ln_in_b = (const float*)d_in[2];
    const float* Wp      = (const float*)d_in[3];
    const float* bp      = (const float*)d_in[4];
    const float* Wg1     = (const float*)d_in[5];
    const float* bg1     = (const float*)d_in[6];
    const float* Wg2     = (const float*)d_in[7];
    const float* bg2     = (const float*)d_in[8];
    const float* Wg3     = (const float*)d_in[9];
    const float* bg3     = (const float*)d_in[10];
    const float* We1     = (const float*)d_in[11];
    const float* be1     = (const float*)d_in[12];
    const float* We2     = (const float*)d_in[13];
    const float* be2     = (const float*)d_in[14];
    const float* We3     = (const float*)d_in[15];
    const float* be3     = (const float*)d_in[16];
    const float* ln_out_g= (const float*)d_in[17];
    const float* ln_out_b= (const float*)d_in[18];
    float* out = (float*)d_out;

    pack_kernel<<<(PACK_TOTAL + 255) / 256, 256>>>(Wp, Wg1, We1, We2);

    const size_t smem = SMEM_FLOATS * sizeof(float);
    cudaFuncSetAttribute(moe_fused_kernel,
                         cudaFuncAttributeMaxDynamicSharedMemorySize, (int)smem);

    moe_fused_kernel<<<B_ / MTILE, NTHREADS, smem>>>(
        x, ln_in_g, ln_in_b, bp, bg1, Wg2, bg2, Wg3, bg3,
        be1, be2, We3, be3, ln_out_g, ln_out_b, out);
}

// round 16
// speedup vs baseline: 2.7147x; 1.0628x over previous
#include <cuda_runtime.h>
#include <math.h>
#include <stdint.h>

// Problem dims
#define B_    262144
#define DIN   153
#define DOUT  8
#define NE    8
#define H1_   128
#define H2_   64
#define GH_   64
#define GH2_  32
#define EPS   1e-5f

#define MTILE 64
#define NTHREADS 256

// k-step / n-tile counts
#define KS_P   20
#define NT_P   20
#define KS_G1  20
#define NT_G1  8
#define KS_E1  20
#define NT_E1P 32
#define KS_E2  16
#define NT_E2  8

// ---- smem layout (floats) ----
// AF block per k-step (64 rows): 2 rg x 2 half x 32 lanes x 4 = 512 floats
#define OFF_XP    0                        // x_norm -> x_proj in-place AF (10240)
#define OFF_H1E0  (OFF_XP + KS_P*512)      // h1 expert-even AF [16 ks] (8192)
#define OFF_H1E1  (OFF_H1E0 + 16*512)      // h1 expert-odd  AF (8192)
#define OFF_G1    OFF_H1E0                 // g1 linear [64][64] (alias, pre-experts)
#define OFF_G2    (OFF_H1E0 + 64*64)       // g2 linear [32][64]
#define OFF_H2P   OFF_H1E0                 // H2 pair [2][64][64] (alias, sync-epi)
#define OFF_GATE  (OFF_H1E1 + 16*512)      // gate [8][64]
#define OFF_ACC   (OFF_GATE + 8*64)        // acc  [2][8][64]
#define SMEM_FLOATS (OFF_ACC + 2*8*64)     // 28160 floats = 112,640 B  (2 CTAs/SM)

// ---- packed-weight global scratch (fragment-lane order) ----
#define SZ_PWP   (KS_P*NT_P*64)
#define SZ_PWG1  (KS_G1*NT_G1*64)
#define SZ_PWE1P (KS_E1*NT_E1P*64)
#define SZ_PWE2  (KS_E2*NT_E2*64)
__device__ float g_pWp  [SZ_PWP];
__device__ float g_pWg1 [SZ_PWG1];
__device__ float g_pWe1p[(NE/2)*SZ_PWE1P];
__device__ float g_pWe2 [NE*SZ_PWE2];
#define PACK_TOTAL (SZ_PWP + SZ_PWG1 + (NE/2)*SZ_PWE1P + NE*SZ_PWE2)

__device__ __forceinline__ float pack_elem(const float* __restrict__ W,
                                           int K, int N, int NT, int rel)
{
    int ks    = rel / (NT * 64);
    int r     = rel % (NT * 64);
    int nt    = r / 64;
    int f     = r % 64;
    int lane  = f >> 1;
    int which = f & 1;
    int tig   = lane & 3;
    int gid   = lane >> 2;
    int k = ks * 8 + which * 4 + tig;
    int n = nt * 8 + gid;
    return (k < K && n < N) ? W[(size_t)k * N + n] : 0.f;
}

__global__ void pack_kernel(const float* __restrict__ Wp,
                            const float* __restrict__ Wg1,
                            const float* __restrict__ We1,
                            const float* __restrict__ We2)
{
    int idx = blockIdx.x * blockDim.x + threadIdx.x;
    if (idx >= PACK_TOTAL) return;
    if (idx < SZ_PWP) { g_pWp[idx] = pack_elem(Wp, DIN, DIN, NT_P, idx); return; }
    idx -= SZ_PWP;
    if (idx < SZ_PWG1) { g_pWg1[idx] = pack_elem(Wg1, DIN, GH_, NT_G1, idx); return; }
    idx -= SZ_PWG1;
    if (idx < (NE/2) * SZ_PWE1P) {
        int p = idx / SZ_PWE1P, rel = idx % SZ_PWE1P;
        int ks = rel / (NT_E1P * 64);
        int r  = rel % (NT_E1P * 64);
        int nt = r / 64;
        int f  = r % 64;
        int lane = f >> 1, which = f & 1;
        int tig = lane & 3, gid = lane >> 2;
        int e  = 2 * p + (nt >= 16 ? 1 : 0);
        int n  = (nt & 15) * 8 + gid;
        int k  = ks * 8 + which * 4 + tig;
        const float* W = We1 + (size_t)e * DIN * H1_;
        g_pWe1p[idx] = (k < DIN) ? W[(size_t)k * H1_ + n] : 0.f;
        return;
    }
    idx -= (NE/2) * SZ_PWE1P;
    {
        int e = idx / SZ_PWE2, rel = idx % SZ_PWE2;
        g_pWe2[idx] = pack_elem(We2 + (size_t)e * H1_ * H2_, H1_, H2_, NT_E2, rel);
    }
}

// ---- AF addressing (64 rows: rg = r>>5 in {0,1}) ----
__device__ __forceinline__ int af_idx(int k, int r) {
    int ks = k >> 3, tigc = k & 3, kbit = (k >> 2) & 1;
    int rg = r >> 5, half = (r >> 4) & 1, gidc = r & 7, rbit = (r >> 3) & 1;
    return ((((ks * 2 + rg) * 2 + half) * 32 + gidc * 4 + tigc) << 2) + kbit * 2 + rbit;
}

// ---- packed f32x2 helpers ----
__device__ __forceinline__ uint64_t fma2(uint64_t a, uint64_t b, uint64_t c) {
    uint64_t d;
    asm("fma.rn.f32x2 %0, %1, %2, %3;" : "=l"(d) : "l"(a), "l"(b), "l"(c));
    return d;
}
__device__ __forceinline__ uint64_t add2(uint64_t a, uint64_t b) {
    uint64_t d;
    asm("add.rn.f32x2 %0, %1, %2;" : "=l"(d) : "l"(a), "l"(b));
    return d;
}
__device__ __forceinline__ uint64_t dup2(float w) {
    uint64_t d;
    asm("mov.b64 %0, {%1, %1};" : "=l"(d) : "f"(w));
    return d;
}
__device__ __forceinline__ void unpack2(uint64_t v, float& lo, float& hi) {
    asm("mov.b64 {%0, %1}, %2;" : "=f"(lo), "=f"(hi) : "l"(v));
}
__device__ __forceinline__ float tf32r(float x) {
    uint32_t u;
    asm("cvt.rna.tf32.f32 %0, %1;" : "=r"(u) : "f"(x));
    return __uint_as_float(u);
}

// ---- warp-level tf32 MMA m16n8k8 ----
__device__ __forceinline__ void mma8(float* d,
                                     uint32_t a0, uint32_t a1, uint32_t a2, uint32_t a3,
                                     uint32_t b0, uint32_t b1) {
    asm volatile(
        "mma.sync.aligned.m16n8k8.row.col.f32.tf32.tf32.f32 "
        "{%0,%1,%2,%3},{%4,%5,%6,%7},{%8,%9},{%0,%1,%2,%3};"
        : "+f"(d[0]), "+f"(d[1]), "+f"(d[2]), "+f"(d[3])
        : "r"(a0), "r"(a1), "r"(a2), "r"(a3), "r"(b0), "r"(b1));
}

// ---- vectorized AF epilogue store (shfl-transpose + STS.128), 2-rg layout ----
template<bool RESID>
__device__ __forceinline__ void epi_af_vec(const float v[2][2],
                                           float* __restrict__ Ot,
                                           const float* __restrict__ Ar,
                                           int nt, int rg, int m, int gid, int tig)
{
    float s00 = __shfl_xor_sync(0xFFFFFFFFu, v[0][0], 2);
    float s01 = __shfl_xor_sync(0xFFFFFFFFu, v[0][1], 2);
    float s10 = __shfl_xor_sync(0xFFFFFFFFu, v[1][0], 2);
    float s11 = __shfl_xor_sync(0xFFFFFFFFu, v[1][1], 2);
    float lo0, lo1, hi0, hi1;
    int tigc;
    if (tig < 2) { lo0 = v[0][0]; lo1 = v[0][1]; hi0 = s00; hi1 = s01; tigc = 2 * tig; }
    else         { lo0 = s10; lo1 = s11; hi0 = v[1][0]; hi1 = v[1][1]; tigc = 2 * (tig - 2) + 1; }
    const int f4 = ((nt * 2 + rg) * 2 + m) * 32 + gid * 4 + tigc;
    if (RESID) {
        float4 old = reinterpret_cast<const float4*>(Ar)[f4];
        lo0 += old.x; lo1 += old.y; hi0 += old.z; hi1 += old.w;
    }
    float4 o;
    o.x = tf32r(lo0); o.y = tf32r(lo1); o.z = tf32r(hi0); o.w = tf32r(hi1);
    reinterpret_cast<float4*>(Ot)[f4] = o;
}

// Tensor-core GEMM: AF A (LDS.128), packed B (LDG.64). 2 rg x 4 cg warps (8 warps).
template<int KS, int NT, int N, bool RELU, bool RESID, bool AFOUT, bool SYNCEPI>
__device__ __forceinline__ void mma_pk(const float* __restrict__ Aaf,
                                       const float* __restrict__ pk,
                                       const float* __restrict__ bias,
                                       float* __restrict__ Ot,
                                       int warp, int lane)
{
    constexpr int NTW = NT / 4;
    const int rg  = warp & 1;
    const int cg  = warp >> 1;           // 0..3
    const int gid = lane >> 2;
    const int tig = lane & 3;

    float acc[NTW][2][4];
    #pragma unroll
    for (int i = 0; i < NTW; i++)
        #pragma unroll
        for (int m = 0; m < 2; m++)
            #pragma unroll
            for (int q = 0; q < 4; q++) acc[i][m][q] = 0.f;

    const float4* __restrict__ afb = reinterpret_cast<const float4*>(Aaf);
    const float2* __restrict__ pb0 = reinterpret_cast<const float2*>(pk) + cg * 32 + lane;

    #pragma unroll 2
    for (int ks = 0; ks < KS; ks++) {
        const float4* ap = afb + ((ks * 2 + rg) * 2) * 32 + lane;
        float4 A = ap[0];
        float4 C = ap[32];
        const float2* pb = pb0 + ks * (NT * 32);
        #pragma unroll
        for (int i = 0; i < NTW; i++) {
            float2 b = pb[i * 128];
            uint32_t b0 = __float_as_uint(b.x), b1 = __float_as_uint(b.y);
            mma8(acc[i][0], __float_as_uint(A.x), __float_as_uint(A.y),
                            __float_as_uint(A.z), __float_as_uint(A.w), b0, b1);
            mma8(acc[i][1], __float_as_uint(C.x), __float_as_uint(C.y),
                            __float_as_uint(C.z), __float_as_uint(C.w), b0, b1);
        }
    }

    if (SYNCEPI) __syncthreads();

    #pragma unroll
    for (int i = 0; i < NTW; i++) {
        const int nt = cg + 4 * i;
        #pragma unroll
        for (int m = 0; m < 2; m++) {
            if (AFOUT) {
                float v[2][2];
                #pragma unroll
                for (int h = 0; h < 2; h++) {
                    const int col = nt * 8 + tig * 2 + h;
                    const bool ok = (N % 8 == 0) || (col < N);
                    const float b = ok ? bias[col] : 0.f;
                    float v0 = acc[i][m][h]     + b;
                    float v1 = acc[i][m][2 + h] + b;
                    if (RELU) { v0 = fmaxf(v0, 0.f); v1 = fmaxf(v1, 0.f); }
                    v[h][0] = ok ? v0 : 0.f;
                    v[h][1] = ok ? v1 : 0.f;
                }
                epi_af_vec<RESID>(v, Ot, Aaf, nt, rg, m, gid, tig);
            } else {
                const int rl = rg * 32 + gid + m * 16;
                const int rh = rl + 8;
                #pragma unroll
                for (int h = 0; h < 2; h++) {
                    const int col = nt * 8 + tig * 2 + h;
                    if ((N % 8 == 0) || (col < N)) {
                        const float b = bias[col];
                        float v0 = acc[i][m][h]     + b;
                        float v1 = acc[i][m][2 + h] + b;
                        if (RELU) { v0 = fmaxf(v0, 0.f); v1 = fmaxf(v1, 0.f); }
                        Ot[col * 64 + rl] = v0;
                        Ot[col * 64 + rh] = v1;
                    }
                }
            }
        }
    }
}

// We1 pair-merged GEMM: N=256 (nt<16 -> h1_e0, nt>=16 -> h1_e1), vectorized AF out.
__device__ __forceinline__ void mma_we1pair(const float* __restrict__ Aaf,
                                            const float* __restrict__ pk,
                                            const float* __restrict__ bias,
                                            float* __restrict__ h1e0,
                                            float* __restrict__ h1e1,
                                            int warp, int lane)
{
    constexpr int NTW = NT_E1P / 4;   // 8
    const int rg  = warp & 1;
    const int cg  = warp >> 1;
    const int gid = lane >> 2;
    const int tig = lane & 3;

    float acc[NTW][2][4];
    #pragma unroll
    for (int i = 0; i < NTW; i++)
        #pragma unroll
        for (int m = 0; m < 2; m++)
            #pragma unroll
            for (int q = 0; q < 4; q++) acc[i][m][q] = 0.f;

    const float4* __restrict__ afb = reinterpret_cast<const float4*>(Aaf);
    const float2* __restrict__ pb0 = reinterpret_cast<const float2*>(pk) + cg * 32 + lane;

    #pragma unroll 2
    for (int ks = 0; ks < KS_E1; ks++) {
        const float4* ap = afb + ((ks * 2 + rg) * 2) * 32 + lane;
        float4 A = ap[0];
        float4 C = ap[32];
        const float2* pb = pb0 + ks * (NT_E1P * 32);
        #pragma unroll
        for (int i = 0; i < NTW; i++) {
            float2 b = pb[i * 128];
            uint32_t b0 = __float_as_uint(b.x), b1 = __float_as_uint(b.y);
            mma8(acc[i][0], __float_as_uint(A.x), __float_as_uint(A.y),
                            __float_as_uint(A.z), __float_as_uint(A.w), b0, b1);
            mma8(acc[i][1], __float_as_uint(C.x), __float_as_uint(C.y),
                            __float_as_uint(C.z), __float_as_uint(C.w), b0, b1);
        }
    }

    __syncthreads();

    #pragma unroll
    for (int i = 0; i < NTW; i++) {
        const int nt  = cg + 4 * i;
        float* __restrict__ Ot = (nt >= 16) ? h1e1 : h1e0;
        const int ntl = nt & 15;
        #pragma unroll
        for (int m = 0; m < 2; m++) {
            float v[2][2];
            #pragma unroll
            for (int h = 0; h < 2; h++) {
                const int col = nt * 8 + tig * 2 + h;
                const float b = bias[col];
                v[h][0] = fmaxf(acc[i][m][h]     + b, 0.f);
                v[h][1] = fmaxf(acc[i][m][2 + h] + b, 0.f);
            }
            epi_af_vec<false>(v, Ot, Ot, ntl, rg, m, gid, tig);
        }
    }
}

// We2 pair-merged: warps 0-3 -> e0 (A=h1e0), 4-7 -> e1 (A=h1e1); linear H2 pair out.
__device__ __forceinline__ void mma_we2pair(const float* __restrict__ smbase,
                                            const float* __restrict__ pkPair,
                                            const float* __restrict__ be2,
                                            float* __restrict__ H2p,
                                            int pairIdx, int warp, int lane)
{
    const int q   = warp >> 2;
    const int w   = warp & 3;
    const int rg  = w & 1;
    const int cg  = w >> 1;        // 0-1
    const int gid = lane >> 2;
    const int tig = lane & 3;
    const int e   = 2 * pairIdx + q;

    const float* Aaf  = smbase + (q ? OFF_H1E1 : OFF_H1E0);
    const float* pk   = pkPair + (size_t)q * SZ_PWE2;
    const float* bias = be2 + e * H2_;

    float acc[4][2][4];
    #pragma unroll
    for (int i = 0; i < 4; i++)
        #pragma unroll
        for (int m = 0; m < 2; m++)
            #pragma unroll
            for (int t = 0; t < 4; t++) acc[i][m][t] = 0.f;

    const float4* __restrict__ afb = reinterpret_cast<const float4*>(Aaf);
    const float2* __restrict__ pb0 = reinterpret_cast<const float2*>(pk) + cg * 32 + lane;

    #pragma unroll 2
    for (int ks = 0; ks < KS_E2; ks++) {
        const float4* ap = afb + ((ks * 2 + rg) * 2) * 32 + lane;
        float4 A = ap[0];
        float4 C = ap[32];
        const float2* pb = pb0 + ks * (NT_E2 * 32);
        #pragma unroll
        for (int i = 0; i < 4; i++) {
            float2 b = pb[i * 64];     // nt = cg + 2*i
            uint32_t b0 = __float_as_uint(b.x), b1 = __float_as_uint(b.y);
            mma8(acc[i][0], __float_as_uint(A.x), __float_as_uint(A.y),
                            __float_as_uint(A.z), __float_as_uint(A.w), b0, b1);
            mma8(acc[i][1], __float_as_uint(C.x), __float_as_uint(C.y),
                            __float_as_uint(C.z), __float_as_uint(C.w), b0, b1);
        }
    }

    __syncthreads();   // all h1 reads done; H2p aliases h1e0 region

    float* __restrict__ Ot = H2p + q * (H2_ * 64);
    #pragma unroll
    for (int i = 0; i < 4; i++) {
        const int nt = cg + 2 * i;
        #pragma unroll
        for (int m = 0; m < 2; m++) {
            const int rl = rg * 32 + gid + m * 16;
            const int rh = rl + 8;
            #pragma unroll
            for (int h = 0; h < 2; h++) {
                const int col = nt * 8 + tig * 2 + h;
                const float b = bias[col];
                Ot[col * 64 + rl] = fmaxf(acc[i][m][h]     + b, 0.f);
                Ot[col * 64 + rh] = fmaxf(acc[i][m][2 + h] + b, 0.f);
            }
        }
    }
}

// Pair combine: warps 0-3 -> e0, 4-7 -> e1; 16 rows/warp, lanes k-quartered.
__device__ __forceinline__ void gemm_combine_pair(const float* __restrict__ H2p,
                                                  const float* __restrict__ We3,
                                                  const float* __restrict__ be3,
                                                  const float* __restrict__ gate,
                                                  float* __restrict__ accP,
                                                  int pairIdx, int warp, int lane)
{
    const int q   = warp >> 2;
    const int w   = warp & 3;
    const int e   = 2 * pairIdx + q;
    const int r0  = w * 16;
    const int col = lane & 7;
    const int kq  = lane >> 3;
    const float* As = H2p + q * (H2_ * 64);
    const float* Wc = We3 + (size_t)e * H2_ * DOUT + kq * 16 * 8 + col;

    uint64_t acc[8];
    #pragma unroll
    for (int j = 0; j < 8; j++) acc[j] = 0ull;

    #pragma unroll 4
    for (int k = 0; k < 16; k++) {
        const float* ap = As + (kq * 16 + k) * 64 + r0;
        ulonglong2 A0 = *(const ulonglong2*)(ap);
        ulonglong2 A1 = *(const ulonglong2*)(ap + 4);
        ulonglong2 A2 = *(const ulonglong2*)(ap + 8);
        ulonglong2 A3 = *(const ulonglong2*)(ap + 12);
        uint64_t wd = dup2(Wc[k * 8]);
        acc[0] = fma2(A0.x, wd, acc[0]); acc[1] = fma2(A0.y, wd, acc[1]);
        acc[2] = fma2(A1.x, wd, acc[2]); acc[3] = fma2(A1.y, wd, acc[3]);
        acc[4] = fma2(A2.x, wd, acc[4]); acc[5] = fma2(A2.y, wd, acc[5]);
        acc[6] = fma2(A3.x, wd, acc[6]); acc[7] = fma2(A3.y, wd, acc[7]);
    }
    #pragma unroll
    for (int j = 0; j < 8; j++) {
        double o16 = __shfl_down_sync(0xFFFFFFFFu,
                                      __longlong_as_double((long long)acc[j]), 16);
        acc[j] = add2(acc[j], (uint64_t)__double_as_longlong(o16));
        double o8 = __shfl_down_sync(0xFFFFFFFFu,
                                     __longlong_as_double((long long)acc[j]), 8);
        acc[j] = add2(acc[j], (uint64_t)__double_as_longlong(o8));
    }
    if (lane < 8) {
        const float b = be3[e * DOUT + col];
        const float* gr = gate + e * 64 + r0;
        float* ap = accP + q * 512 + col * 64 + r0;
        #pragma unroll
        for (int j = 0; j < 8; j++) {
            float lo, hi;
            unpack2(acc[j], lo, hi);
            ap[2 * j]     += gr[2 * j]     * (lo + b);
            ap[2 * j + 1] += gr[2 * j + 1] * (hi + b);
        }
    }
}

// Scalar FFMA2 GEMM (small gating layers, fp32), linear layouts stride 64
template<int K, int N, bool RELU>
__device__ __forceinline__ void gemmT(const float* __restrict__ As,
                                      const float* __restrict__ W,
                                      const float* __restrict__ bias,
                                      float* __restrict__ Ot,
                                      int tr, int tc)
{
    const int r0 = tr * 8;
    uint64_t acc[4][4];
    #pragma unroll
    for (int j = 0; j < 4; j++)
        #pragma unroll
        for (int q = 0; q < 4; q++) acc[j][q] = 0ull;

    const float* __restrict__ Wc[4];
    bool ok[4];
    #pragma unroll
    for (int j = 0; j < 4; j++) {
        if (32 * j < N) {
            int col = 32 * j + tc;
            ok[j] = (col < N);
            Wc[j] = W + (ok[j] ? col : 0);
        }
    }
    #pragma unroll 4
    for (int k = 0; k < K; k++) {
        const float* ap = As + k * 64 + r0;
        ulonglong2 A0 = *(const ulonglong2*)(ap);
        ulonglong2 A1 = *(const ulonglong2*)(ap + 4);
        #pragma unroll
        for (int j = 0; j < 4; j++) {
            if (32 * j < N) {
                uint64_t wd = dup2(Wc[j][(size_t)k * N]);
                acc[j][0] = fma2(A0.x, wd, acc[j][0]);
                acc[j][1] = fma2(A0.y, wd, acc[j][1]);
                acc[j][2] = fma2(A1.x, wd, acc[j][2]);
                acc[j][3] = fma2(A1.y, wd, acc[j][3]);
            }
        }
    }
    #pragma unroll
    for (int j = 0; j < 4; j++) {
        if (32 * j < N) {
            int col = 32 * j + tc;
            if (ok[j]) {
                const float b = bias[col];
                float* op = Ot + col * 64 + r0;
                #pragma unroll
                for (int q = 0; q < 4; q++) {
                    float lo, hi;
                    unpack2(acc[j][q], lo, hi);
                    float v0 = lo + b, v1 = hi + b;
                    if (RELU) { v0 = fmaxf(v0, 0.f); v1 = fmaxf(v1, 0.f); }
                    op[2 * q]     = v0;
                    op[2 * q + 1] = v1;
                }
            }
        }
    }
}

__global__ __launch_bounds__(NTHREADS, 2)
void moe_fused_kernel(const float* __restrict__ x,
                      const float* __restrict__ ln_in_g, const float* __restrict__ ln_in_b,
                      const float* __restrict__ bp,
                      const float* __restrict__ bg1,
                      const float* __restrict__ Wg2, const float* __restrict__ bg2,
                      const float* __restrict__ Wg3, const float* __restrict__ bg3,
                      const float* __restrict__ be1,
                      const float* __restrict__ be2,
                      const float* __restrict__ We3, const float* __restrict__ be3,
                      const float* __restrict__ ln_out_g, const float* __restrict__ ln_out_b,
                      float* __restrict__ out)
{
    extern __shared__ float sm[];
    const int tid  = threadIdx.x;
    const int tr   = tid >> 5, tc = tid & 31;
    const int warp = tid >> 5, lane = tid & 31;
    const int row0 = blockIdx.x * MTILE;

    // zero both ACC buffers and the XP pad k-step (k=152..159); barrier before LN.
    for (int i = tid; i < 2 * 8 * 64; i += NTHREADS) sm[OFF_ACC + i] = 0.f;
    for (int i = tid; i < 512; i += NTHREADS)
        sm[OFF_XP + (KS_P - 1) * 512 + i] = 0.f;
    __syncthreads();

    // ---- input LayerNorm -> XP (AF, tf32-rounded) ----
    for (int rr = warp; rr < MTILE; rr += 8) {
        const float* xr = x + (size_t)(row0 + rr) * DIN;
        float v[5];
        float s = 0.f, ss = 0.f;
        #pragma unroll
        for (int i = 0; i < 5; i++) {
            int k = i * 32 + lane;
            float val = (k < DIN) ? xr[k] : 0.f;
            v[i] = val; s += val; ss += val * val;
        }
        #pragma unroll
        for (int o = 16; o > 0; o >>= 1) {
            s  += __shfl_xor_sync(0xFFFFFFFFu, s,  o);
            ss += __shfl_xor_sync(0xFFFFFFFFu, ss, o);
        }
        const float m   = s * (1.f / DIN);
        const float var = ss * (1.f / DIN) - m * m;
        const float inv = rsqrtf(var + EPS);
        #pragma unroll
        for (int i = 0; i < 5; i++) {
            int k = i * 32 + lane;
            if (k < DIN)
                sm[OFF_XP + af_idx(k, rr)] =
                    tf32r((v[i] - m) * inv * ln_in_g[k] + ln_in_b[k]);
        }
    }
    __syncthreads();

    // ---- x_proj = relu(x_norm @ Wp + bp) + x_norm  (IN-PLACE, vec epi) ----
    mma_pk<KS_P, NT_P, DIN, true, true, true, true>(sm + OFF_XP, g_pWp, bp,
                                                    sm + OFF_XP, warp, lane);
    __syncthreads();

    // ---- gating: g1 tensor (linear out), g2/g3 scalar ----
    mma_pk<KS_G1, NT_G1, GH_, true, false, false, false>(sm + OFF_XP, g_pWg1, bg1,
                                                         sm + OFF_G1, warp, lane);
    __syncthreads();
    gemmT<GH_, GH2_, true>(sm + OFF_G1, Wg2, bg2, sm + OFF_G2, tr, tc);
    __syncthreads();
    gemmT<GH2_, 8, false>(sm + OFF_G2, Wg3, bg3, sm + OFF_GATE, tr, tc);
    __syncthreads();

    // ---- softmax over experts, write gating output ----
    if (tid < MTILE) {
        float l[8];
        float mx = -INFINITY;
        #pragma unroll
        for (int e = 0; e < NE; e++) { l[e] = sm[OFF_GATE + e * 64 + tid]; mx = fmaxf(mx, l[e]); }
        float s = 0.f;
        #pragma unroll
        for (int e = 0; e < NE; e++) { l[e] = expf(l[e] - mx); s += l[e]; }
        const float invs = 1.f / s;
        float* gw = out + (size_t)B_ * 8 + (size_t)(row0 + tid) * 8;
        #pragma unroll
        for (int e = 0; e < NE; e++) {
            float g = l[e] * invs;
            sm[OFF_GATE + e * 64 + tid] = g;
            gw[e] = g;
        }
    }
    __syncthreads();

    // ---- experts: 4 pair-passes, fully pair-parallel ----
    #pragma unroll 1
    for (int p = 0; p < NE / 2; p++) {
        mma_we1pair(sm + OFF_XP, g_pWe1p + (size_t)p * SZ_PWE1P,
                    be1 + 2 * p * H1_, sm + OFF_H1E0, sm + OFF_H1E1, warp, lane);
        __syncthreads();
        mma_we2pair(sm, g_pWe2 + (size_t)(2 * p) * SZ_PWE2, be2,
                    sm + OFF_H2P, p, warp, lane);
        __syncthreads();
        gemm_combine_pair(sm + OFF_H2P, We3, be3, sm + OFF_GATE,
                          sm + OFF_ACC, p, warp, lane);
        __syncthreads();
    }

    // ---- output LayerNorm over 8 dims (sum both ACC buffers), write out ----
    if (tid < MTILE) {
        float y[8];
        float s = 0.f;
        #pragma unroll
        for (int e = 0; e < DOUT; e++) {
            y[e] = sm[OFF_ACC + e * 64 + tid] + sm[OFF_ACC + 512 + e * 64 + tid];
            s += y[e];
        }
        const float m = s * 0.125f;
        float var = 0.f;
        #pragma unroll
        for (int e = 0; e < DOUT; e++) { float d = y[e] - m; var += d * d; }
        var *= 0.125f;
        const float inv = rsqrtf(var + EPS);
        float* op = out + (size_t)(row0 + tid) * 8;
        #pragma unroll
        for (int e = 0; e < DOUT; e++)
            op[e] = (y[e] - m) * inv * ln_out_g[e] + ln_out_b[e];
    }
}

extern "C" void kernel_launch(void* const* d_in, const int* in_sizes, int n_in,
                              void* d_out, int out_size)
{
    const float* x       = (const float*)d_in[0];
    const float* ln_in_g = (const float*)d_in[1];
    const float* ln_in_b = (const float*)d_in[2];
    const float* Wp      = (const float*)d_in[3];
    const float* bp      = (const float*)d_in[4];
    const float* Wg1     = (const float*)d_in[5];
    const float* bg1     = (const float*)d_in[6];
    const float* Wg2     = (const float*)d_in[7];
    const float* bg2     = (const float*)d_in[8];
    const float* Wg3     = (const float*)d_in[9];
    const float* bg3     = (const float*)d_in[10];
    const float* We1     = (const float*)d_in[11];
    const float* be1     = (const float*)d_in[12];
    const float* We2     = (const float*)d_in[13];
    const float* be2     = (const float*)d_in[14];
    const float* We3     = (const float*)d_in[15];
    const float* be3     = (const float*)d_in[16];
    const float* ln_out_g= (const float*)d_in[17];
    const float* ln_out_b= (const float*)d_in[18];
    float* out = (float*)d_out;

    pack_kernel<<<(PACK_TOTAL + 255) / 256, 256>>>(Wp, Wg1, We1, We2);

    const size_t smem = SMEM_FLOATS * sizeof(float);
    cudaFuncSetAttribute(moe_fused_kernel,
                         cudaFuncAttributeMaxDynamicSharedMemorySize, (int)smem);

    moe_fused_kernel<<<B_ / MTILE, NTHREADS, smem>>>(
        x, ln_in_g, ln_in_b, bp, bg1, Wg2, bg2, Wg3, bg3,
        be1, be2, We3, be3, ln_out_g, ln_out_b, out);
}